// round 8
// baseline (speedup 1.0000x reference)
#include <cuda_runtime.h>
#include <cuda_bf16.h>
#include <cstdint>

#define BSZ 2
#define NH 16
#define SEQ 2048
#define DM 1024
#define HD 64
#define BH (BSZ*NH)

// Scratch (device globals — no allocations allowed)
__device__ __nv_bfloat16 g_xh[BSZ*SEQ*DM];
__device__ __nv_bfloat16 g_xl[BSZ*SEQ*DM];
__device__ __nv_bfloat16 g_wh[3*DM*DM];
__device__ __nv_bfloat16 g_wl[3*DM*DM];
__device__ __nv_bfloat16 g_q_hi[BH * SEQ * HD];
__device__ __nv_bfloat16 g_q_lo[BH * SEQ * HD];
__device__ __nv_bfloat16 g_k_hi[BH * SEQ * HD];
__device__ __nv_bfloat16 g_k_lo[BH * SEQ * HD];
__device__ __nv_bfloat16 g_v_hi[BH * SEQ * HD];
__device__ __nv_bfloat16 g_v_lo[BH * SEQ * HD];

// ---- bf16 split: hi = bf16x2(a,b); lo = bf16x2 residual ---------------------
__device__ __forceinline__ void split2(float a, float b, uint32_t& hi, uint32_t& lo) {
    __nv_bfloat162 h = __floats2bfloat162_rn(a, b);
    float2 hf = __bfloat1622float2(h);
    __nv_bfloat162 l = __floats2bfloat162_rn(a - hf.x, b - hf.y);
    hi = *reinterpret_cast<uint32_t*>(&h);
    lo = *reinterpret_cast<uint32_t*>(&l);
}

// ---- smem / ldmatrix / mma / cp.async primitives ----------------------------
__device__ __forceinline__ uint32_t smem_u32(const void* p) {
    uint32_t a;
    asm("{ .reg .u64 t; cvta.to.shared.u64 t, %1; cvt.u32.u64 %0, t; }"
        : "=r"(a) : "l"(p));
    return a;
}
// 128B-row tiles: XOR 16B-chunk by (row&7)
__device__ __forceinline__ uint32_t swz_addr(uint32_t base, int row, int chunk) {
    uint32_t off = (uint32_t)(row * 128 + chunk * 16);
    return base + (off ^ ((off >> 3) & 0x70));
}
// 64B-row tiles: SW64 swizzle
__device__ __forceinline__ uint32_t swz64_addr(uint32_t base, int row, int chunk) {
    uint32_t off = (uint32_t)(row * 64 + chunk * 16);
    return base + (off ^ ((off >> 3) & 0x30));
}
__device__ __forceinline__ void ldsm_x4(uint32_t* r, uint32_t a) {
    asm volatile("ldmatrix.sync.aligned.m8n8.x4.shared.b16 {%0,%1,%2,%3}, [%4];"
        : "=r"(r[0]), "=r"(r[1]), "=r"(r[2]), "=r"(r[3]) : "r"(a));
}
__device__ __forceinline__ void ldsm_x4t(uint32_t* r, uint32_t a) {
    asm volatile("ldmatrix.sync.aligned.m8n8.x4.trans.shared.b16 {%0,%1,%2,%3}, [%4];"
        : "=r"(r[0]), "=r"(r[1]), "=r"(r[2]), "=r"(r[3]) : "r"(a));
}
__device__ __forceinline__ void mma_bf16(float* d, const uint32_t* a,
                                         uint32_t b0, uint32_t b1) {
    asm volatile("mma.sync.aligned.m16n8k16.row.col.f32.bf16.bf16.f32 "
        "{%0,%1,%2,%3}, {%4,%5,%6,%7}, {%8,%9}, {%0,%1,%2,%3};"
        : "+f"(d[0]), "+f"(d[1]), "+f"(d[2]), "+f"(d[3])
        : "r"(a[0]), "r"(a[1]), "r"(a[2]), "r"(a[3]), "r"(b0), "r"(b1));
}
__device__ __forceinline__ void cp16(uint32_t dst, const void* src) {
    asm volatile("cp.async.cg.shared.global [%0], [%1], 16;"
                 :: "r"(dst), "l"(src) : "memory");
}
__device__ __forceinline__ void pref_l2(const void* p) {
    asm volatile("prefetch.global.L2 [%0];" :: "l"(p));
}
#define CP_COMMIT() asm volatile("cp.async.commit_group;" ::: "memory")
#define CP_WAIT1()  asm volatile("cp.async.wait_group 1;" ::: "memory")

// ---------------------------------------------------------------------------
// Kernel 0: split fp32 sources into hi/lo bf16 buffers (x, wq, wk, wv).
// ---------------------------------------------------------------------------
__global__ __launch_bounds__(256) void split_src_kernel(
    const float* __restrict__ x,
    const float* __restrict__ wq, const float* __restrict__ wk,
    const float* __restrict__ wv)
{
    const int z = blockIdx.y;
    const float* src;
    uint32_t *oh, *ol;
    size_t n2;
    if (z == 0) {
        src = x; oh = (uint32_t*)g_xh; ol = (uint32_t*)g_xl;
        n2 = (size_t)BSZ * SEQ * DM / 2;
    } else {
        src = (z == 1) ? wq : (z == 2) ? wk : wv;
        oh = (uint32_t*)(g_wh + (size_t)(z - 1) * DM * DM);
        ol = (uint32_t*)(g_wl + (size_t)(z - 1) * DM * DM);
        n2 = (size_t)DM * DM / 2;
    }
    for (size_t i = (size_t)blockIdx.x * 256 + threadIdx.x; i < n2;
         i += (size_t)gridDim.x * 256) {
        float2 v = ((const float2*)src)[i];
        uint32_t hi, lo;
        split2(v.x, v.y, hi, lo);
        oh[i] = hi; ol[i] = lo;
    }
}

// ---------------------------------------------------------------------------
// Kernel 1: QKV projection via HMMA bf16x3. 128x128 tile, K-slab 32,
// warps tiled 4(M)x2(N): warp = 32 rows x 64 cols (less redundant ldsm).
// ---------------------------------------------------------------------------
#define QKV_SMEM_BYTES 65536

__global__ __launch_bounds__(256, 2) void qkv_hmma_kernel(
    const float* __restrict__ bq, const float* __restrict__ bk,
    const float* __restrict__ bv)
{
    extern __shared__ char smem[];
    const uint32_t sb = smem_u32(smem);
    const int tid = threadIdx.x, wid = tid >> 5, lane = tid & 31;
    const int wm = wid & 3, wn = wid >> 2;
    const int z = blockIdx.z;
    const float* bvec = (z == 0) ? bq : (z == 1) ? bk : bv;
    __nv_bfloat16* ohi = (z == 0) ? g_q_hi : (z == 1) ? g_k_hi : g_v_hi;
    __nv_bfloat16* olo = (z == 0) ? g_q_lo : (z == 1) ? g_k_lo : g_v_lo;
    const __nv_bfloat16* WH = g_wh + (size_t)z * DM * DM;
    const __nv_bfloat16* WL = g_wl + (size_t)z * DM * DM;
    const int col0 = blockIdx.x << 7;
    const int row0 = blockIdx.y << 7;

    auto issue = [&](int slab, int buf) {
        const int k0 = slab << 5;
        const uint32_t base = sb + (uint32_t)buf * 32768;
        #pragma unroll
        for (int it = 0; it < 2; it++) {
            const int idx = tid + it * 256;     // 0..511
            const int r = idx >> 2, c = idx & 3;
            uint32_t off = (uint32_t)(r * 64 + c * 16);
            off ^= (off >> 3) & 0x30;
            const size_t gx = (size_t)(row0 + r) * DM + k0 + c * 8;
            const size_t gw = (size_t)(col0 + r) * DM + k0 + c * 8;
            cp16(base + off,         g_xh + gx);
            cp16(base + 8192 + off,  g_xl + gx);
            cp16(base + 16384 + off, WH + gw);
            cp16(base + 24576 + off, WL + gw);
        }
    };

    float s[2][8][4];
    #pragma unroll
    for (int m = 0; m < 2; m++)
        #pragma unroll
        for (int g = 0; g < 8; g++)
            #pragma unroll
            for (int j = 0; j < 4; j++) s[m][g][j] = 0.0f;

    issue(0, 0);
    CP_COMMIT();

    for (int kt = 0; kt < 32; kt++) {
        if (kt) __syncthreads();
        if (kt < 31) issue(kt + 1, (kt + 1) & 1);
        CP_COMMIT();
        CP_WAIT1();
        __syncthreads();

        const uint32_t base = sb + (uint32_t)(kt & 1) * 32768;
        // A fragments: 2 m16 tiles per warp
        uint32_t ah[2][2][4], al[2][2][4];
        #pragma unroll
        for (int m = 0; m < 2; m++) {
            const int rA = (wm << 5) + (m << 4) + (lane & 7) + ((lane >> 3) & 1) * 8;
            #pragma unroll
            for (int ks = 0; ks < 2; ks++) {
                const int ch = ks * 2 + (lane >> 4);
                ldsm_x4(ah[m][ks], swz64_addr(base,        rA, ch));
                ldsm_x4(al[m][ks], swz64_addr(base + 8192, rA, ch));
            }
        }
        #pragma unroll
        for (int ks = 0; ks < 2; ks++) {
            #pragma unroll
            for (int nf = 0; nf < 4; nf++) {
                const int rB = (wn << 6) + nf * 16 + (lane & 7) + (lane >> 4) * 8;
                const int ch = ks * 2 + ((lane >> 3) & 1);
                uint32_t wh4[4], wl4[4];
                ldsm_x4(wh4, swz64_addr(base + 16384, rB, ch));
                ldsm_x4(wl4, swz64_addr(base + 24576, rB, ch));
                #pragma unroll
                for (int m = 0; m < 2; m++) {
                    mma_bf16(s[m][2*nf],   ah[m][ks], wh4[0], wh4[1]);
                    mma_bf16(s[m][2*nf+1], ah[m][ks], wh4[2], wh4[3]);
                    mma_bf16(s[m][2*nf],   ah[m][ks], wl4[0], wl4[1]);
                    mma_bf16(s[m][2*nf+1], ah[m][ks], wl4[2], wl4[3]);
                    mma_bf16(s[m][2*nf],   al[m][ks], wh4[0], wh4[1]);
                    mma_bf16(s[m][2*nf+1], al[m][ks], wh4[2], wh4[3]);
                }
            }
        }
    }

    // epilogue: + bias, split to hi/lo, store head-split
    #pragma unroll
    for (int m = 0; m < 2; m++) {
        const int r1 = row0 + (wm << 5) + (m << 4) + (lane >> 2);
        const int r2 = r1 + 8;
        const int bb1 = r1 >> 11, ss1 = r1 & (SEQ - 1);
        const int bb2 = r2 >> 11, ss2 = r2 & (SEQ - 1);
        #pragma unroll
        for (int g = 0; g < 8; g++) {
            const int c = col0 + (wn << 6) + g * 8 + (lane & 3) * 2;
            const int h = c >> 6, d = c & 63;
            float2 b2 = *(const float2*)(bvec + c);
            uint32_t hi, lo;
            split2(s[m][g][0] + b2.x, s[m][g][1] + b2.y, hi, lo);
            const size_t e1 = (((size_t)bb1 * NH + h) * SEQ + ss1) * HD + d;
            *(uint32_t*)&ohi[e1] = hi; *(uint32_t*)&olo[e1] = lo;
            split2(s[m][g][2] + b2.x, s[m][g][3] + b2.y, hi, lo);
            const size_t e2 = (((size_t)bb2 * NH + h) * SEQ + ss2) * HD + d;
            *(uint32_t*)&ohi[e2] = hi; *(uint32_t*)&olo[e2] = lo;
        }
    }
}

// ---------------------------------------------------------------------------
// Kernel 2: HMMA attention, bf16x3, 64-wide k-tiles, 2 CTAs/SM,
// hoisted Q fragments, bias L2 prefetch, interleaved epilogue+PV,
// fused attn rescale.
// ---------------------------------------------------------------------------
#define SM_QH 0
#define SM_QL 16384
#define SM_TILES 32768                 // + buf*32768: KH+0, KL+8K, VH+16K, VL+24K
#define ATTN_SMEM_BYTES 98304

__global__ __launch_bounds__(256, 2) void attn_mma_kernel(
    const float* __restrict__ bias,
    const int*   __restrict__ mask,
    float* __restrict__ outp,
    float* __restrict__ attn)
{
    extern __shared__ char smem[];
    const uint32_t sb = smem_u32(smem);

    const int tid = threadIdx.x;
    const int wid = tid >> 5, lane = tid & 31;
    const int bh = blockIdx.y;
    const int h  = bh & (NH - 1);
    const int q0 = blockIdx.x << 7;
    const float scale = 0.125f;
    const size_t bhbase = (size_t)bh * SEQ;

    auto issue_kv = [&](int kt, int buf) {
        const int k0 = kt << 6;
        const uint32_t base = sb + SM_TILES + (uint32_t)buf * 32768;
        const char* kh = (const char*)(g_k_hi + (bhbase + k0) * HD);
        const char* kl = (const char*)(g_k_lo + (bhbase + k0) * HD);
        const char* vh = (const char*)(g_v_hi + (bhbase + k0) * HD);
        const char* vl = (const char*)(g_v_lo + (bhbase + k0) * HD);
        #pragma unroll
        for (int it = 0; it < 2; it++) {
            const int idx = tid + it * 256;     // 0..511
            const uint32_t off = (uint32_t)(idx << 4);
            const uint32_t dst = off ^ ((off >> 3) & 0x70);
            cp16(base + dst,         kh + off);
            cp16(base + 8192 + dst,  kl + off);
            cp16(base + 16384 + dst, vh + off);
            cp16(base + 24576 + dst, vl + off);
        }
    };

    // prologue: Q tiles + K/V(0)
    {
        const char* qh = (const char*)(g_q_hi + (bhbase + q0) * HD);
        const char* ql = (const char*)(g_q_lo + (bhbase + q0) * HD);
        #pragma unroll
        for (int it = 0; it < 4; it++) {
            const int idx = tid + it * 256;     // 0..1023
            const uint32_t off = (uint32_t)(idx << 4);
            const uint32_t dst = off ^ ((off >> 3) & 0x70);
            cp16(sb + SM_QH + dst, qh + off);
            cp16(sb + SM_QL + dst, ql + off);
        }
    }
    issue_kv(0, 0);
    CP_COMMIT();

    float o[8][4];
    #pragma unroll
    for (int g = 0; g < 8; g++)
        #pragma unroll
        for (int j = 0; j < 4; j++) o[g][j] = 0.0f;
    float rsum1 = 0.0f, rsum2 = 0.0f;
    uint32_t qfh[4][4], qfl[4][4];     // hoisted Q fragments

    const int r1 = (wid << 4) + (lane >> 2);
    const int qg1 = q0 + r1, qg2 = qg1 + 8;
    const float* brow1 = bias + ((size_t)h * SEQ + qg1) * SEQ;
    const float* brow2 = bias + ((size_t)h * SEQ + qg2) * SEQ;
    const int*   mrow1 = mask + (size_t)qg1 * SEQ;
    const int*   mrow2 = mask + (size_t)qg2 * SEQ;
    float*       arow1 = attn + (bhbase + qg1) * SEQ;
    float*       arow2 = attn + (bhbase + qg2) * SEQ;

    const int rA = (wid << 4) + (lane & 7) + ((lane >> 3) & 1) * 8;

    for (int kt = 0; kt < SEQ / 64; kt++) {
        const int k0 = kt << 6;
        if (kt) __syncthreads();
        if (kt < SEQ / 64 - 1) issue_kv(kt + 1, (kt + 1) & 1);
        CP_COMMIT();
        CP_WAIT1();
        __syncthreads();

        if (kt == 0) {                  // hoist Q fragments once
            #pragma unroll
            for (int ks = 0; ks < 4; ks++) {
                const int chA = ks * 2 + (lane >> 4);
                ldsm_x4(qfh[ks], swz_addr(sb + SM_QH, rA, chA));
                ldsm_x4(qfl[ks], swz_addr(sb + SM_QL, rA, chA));
            }
        }

        // L2-prefetch next tile's bias rows (2 rows x 256B)
        if (kt < SEQ / 64 - 1 && lane < 4) {
            const float* pb = (lane & 1) ? brow2 : brow1;
            pref_l2(pb + k0 + 64 + (lane >> 1) * 32);
        }

        const uint32_t base = sb + SM_TILES + (uint32_t)(kt & 1) * 32768;

        // ---- S = Q K^T over 64 cols (8 n8-groups), bf16x3 ----
        float s[8][4];
        #pragma unroll
        for (int g = 0; g < 8; g++)
            #pragma unroll
            for (int j = 0; j < 4; j++) s[g][j] = 0.0f;

        #pragma unroll
        for (int ks = 0; ks < 4; ks++) {
            #pragma unroll
            for (int nf = 0; nf < 4; nf++) {
                const int rB = nf * 16 + (lane & 7) + (lane >> 4) * 8;
                const int ch = ks * 2 + ((lane >> 3) & 1);
                uint32_t kh4[4], kl4[4];
                ldsm_x4(kh4, swz_addr(base,        rB, ch));
                ldsm_x4(kl4, swz_addr(base + 8192, rB, ch));
                mma_bf16(s[2*nf],   qfh[ks], kh4[0], kh4[1]);
                mma_bf16(s[2*nf+1], qfh[ks], kh4[2], kh4[3]);
                mma_bf16(s[2*nf],   qfh[ks], kl4[0], kl4[1]);
                mma_bf16(s[2*nf+1], qfh[ks], kl4[2], kl4[3]);
                mma_bf16(s[2*nf],   qfl[ks], kh4[0], kh4[1]);
                mma_bf16(s[2*nf+1], qfl[ks], kh4[2], kh4[3]);
            }
        }

        // ---- per 16-k chunk: epilogue then PV (interleaved) ----
        #pragma unroll
        for (int kc = 0; kc < 4; kc++) {
            uint32_t ph[4], pl[4];
            #pragma unroll
            for (int gi = 0; gi < 2; gi++) {
                const int g = 2 * kc + gi;
                const int c = k0 + g * 8 + (lane & 3) * 2;
                float2 bA = *(const float2*)(brow1 + c);
                float2 bB = *(const float2*)(brow2 + c);
                int2   mA = *(const int2*)(mrow1 + c);
                int2   mB = *(const int2*)(mrow2 + c);
                float p0 = mA.x ? __expf(fmaf(s[g][0], scale, bA.x)) : 0.0f;
                float p1 = mA.y ? __expf(fmaf(s[g][1], scale, bA.y)) : 0.0f;
                float p2 = mB.x ? __expf(fmaf(s[g][2], scale, bB.x)) : 0.0f;
                float p3 = mB.y ? __expf(fmaf(s[g][3], scale, bB.y)) : 0.0f;
                rsum1 += p0 + p1;
                rsum2 += p2 + p3;
                *(float2*)(arow1 + c) = make_float2(p0, p1);
                *(float2*)(arow2 + c) = make_float2(p2, p3);
                split2(p0, p1, ph[gi * 2 + 0], pl[gi * 2 + 0]);
                split2(p2, p3, ph[gi * 2 + 1], pl[gi * 2 + 1]);
            }
            const int rV = kc * 16 + (lane & 7) + ((lane >> 3) & 1) * 8;
            #pragma unroll
            for (int dg = 0; dg < 4; dg++) {
                const int ch = 2 * dg + (lane >> 4);
                uint32_t vh4[4], vl4[4];
                ldsm_x4t(vh4, swz_addr(base + 16384, rV, ch));
                ldsm_x4t(vl4, swz_addr(base + 24576, rV, ch));
                mma_bf16(o[2*dg],   ph, vh4[0], vh4[1]);
                mma_bf16(o[2*dg+1], ph, vh4[2], vh4[3]);
                mma_bf16(o[2*dg],   ph, vl4[0], vl4[1]);
                mma_bf16(o[2*dg+1], ph, vl4[2], vl4[3]);
                mma_bf16(o[2*dg],   pl, vh4[0], vh4[1]);
                mma_bf16(o[2*dg+1], pl, vh4[2], vh4[3]);
            }
        }
    }

    // ---- rowsum quad-reduce ----
    rsum1 += __shfl_xor_sync(0xffffffffu, rsum1, 1);
    rsum1 += __shfl_xor_sync(0xffffffffu, rsum1, 2);
    rsum2 += __shfl_xor_sync(0xffffffffu, rsum2, 1);
    rsum2 += __shfl_xor_sync(0xffffffffu, rsum2, 2);
    const float inv1 = 1.0f / rsum1;
    const float inv2 = 1.0f / rsum2;

    // normalized O
    float* or1 = outp + (bhbase + qg1) * HD;
    float* or2 = outp + (bhbase + qg2) * HD;
    #pragma unroll
    for (int g = 0; g < 8; g++) {
        const int c = g * 8 + (lane & 3) * 2;
        *(float2*)(or1 + c) = make_float2(o[g][0] * inv1, o[g][1] * inv1);
        *(float2*)(or2 + c) = make_float2(o[g][2] * inv2, o[g][3] * inv2);
    }

    // ---- fused attn rescale: warp rescales its own 16 rows ----
    float* rs = (float*)smem;          // 128 floats; KV smem no longer needed
    __syncthreads();                   // all attn stores done; smem free
    if ((lane & 3) == 0) {
        rs[r1] = inv1;
        rs[qg2 - q0] = inv2;
    }
    __syncthreads();
    #pragma unroll 1
    for (int rr = 0; rr < 16; rr++) {
        const int qr = (wid << 4) + rr;
        const float inv = rs[qr];
        float4* row = (float4*)(attn + (bhbase + q0 + qr) * SEQ);
        #pragma unroll 4
        for (int c = lane; c < SEQ / 4; c += 32) {
            float4 v = row[c];
            v.x *= inv; v.y *= inv; v.z *= inv; v.w *= inv;
            row[c] = v;
        }
    }
}

// ---------------------------------------------------------------------------
extern "C" void kernel_launch(void* const* d_in, const int* in_sizes, int n_in,
                              void* d_out, int out_size)
{
    const float* x    = (const float*)d_in[0];
    const float* bias = (const float*)d_in[1];
    const int*   mask = (const int*)d_in[2];
    const float* wq   = (const float*)d_in[3];
    const float* bq   = (const float*)d_in[4];
    const float* wk   = (const float*)d_in[5];
    const float* bk   = (const float*)d_in[6];
    const float* wv   = (const float*)d_in[7];
    const float* bv   = (const float*)d_in[8];

    float* outp = (float*)d_out;                       // [2,16,2048,64]
    float* attn = outp + (size_t)BH * SEQ * HD;        // [2,16,2048,2048]

    cudaFuncSetAttribute(qkv_hmma_kernel,
                         cudaFuncAttributeMaxDynamicSharedMemorySize,
                         QKV_SMEM_BYTES);
    cudaFuncSetAttribute(attn_mma_kernel,
                         cudaFuncAttributeMaxDynamicSharedMemorySize,
                         ATTN_SMEM_BYTES);

    // 0) split x / W into hi+lo bf16
    split_src_kernel<<<dim3(2048, 4), 256>>>(x, wq, wk, wv);

    // 1) QKV projections (HMMA bf16x3) -> split-bf16 Q/K/V
    qkv_hmma_kernel<<<dim3(DM / 128, (BSZ * SEQ) / 128, 3), 256,
                      QKV_SMEM_BYTES>>>(bq, bk, bv);

    // 2) HMMA fused attention + fused rescale
    attn_mma_kernel<<<dim3(SEQ / 128, BH), 256, ATTN_SMEM_BYTES>>>(
        bias, mask, outp, attn);
}

// round 9
// speedup vs baseline: 1.0791x; 1.0791x over previous
#include <cuda_runtime.h>
#include <cuda_bf16.h>
#include <cuda_fp16.h>
#include <cstdint>

#define BSZ 2
#define NH 16
#define SEQ 2048
#define DM 1024
#define HD 64
#define BH (BSZ*NH)

// Scratch (device globals — no allocations allowed)
__device__ __nv_bfloat16 g_xh[BSZ*SEQ*DM];
__device__ __nv_bfloat16 g_xl[BSZ*SEQ*DM];
__device__ __nv_bfloat16 g_wh[3*DM*DM];
__device__ __nv_bfloat16 g_wl[3*DM*DM];
__device__ __nv_bfloat16 g_q_hi[BH * SEQ * HD];
__device__ __nv_bfloat16 g_q_lo[BH * SEQ * HD];
__device__ __nv_bfloat16 g_k_hi[BH * SEQ * HD];
__device__ __nv_bfloat16 g_k_lo[BH * SEQ * HD];
__device__ __half        g_vh [BH * SEQ * HD];   // V: single fp16 (11-bit mantissa)

// ---- bf16 split: hi = bf16x2(a,b); lo = bf16x2 residual ---------------------
__device__ __forceinline__ void split2(float a, float b, uint32_t& hi, uint32_t& lo) {
    __nv_bfloat162 h = __floats2bfloat162_rn(a, b);
    float2 hf = __bfloat1622float2(h);
    __nv_bfloat162 l = __floats2bfloat162_rn(a - hf.x, b - hf.y);
    hi = *reinterpret_cast<uint32_t*>(&h);
    lo = *reinterpret_cast<uint32_t*>(&l);
}
// ---- fp16 split -------------------------------------------------------------
__device__ __forceinline__ void split2h(float a, float b, uint32_t& hi, uint32_t& lo) {
    __half2 h = __floats2half2_rn(a, b);
    float2 hf = __half22float2(h);
    __half2 l = __floats2half2_rn(a - hf.x, b - hf.y);
    hi = *reinterpret_cast<uint32_t*>(&h);
    lo = *reinterpret_cast<uint32_t*>(&l);
}

// ---- smem / ldmatrix / mma / cp.async primitives ----------------------------
__device__ __forceinline__ uint32_t smem_u32(const void* p) {
    uint32_t a;
    asm("{ .reg .u64 t; cvta.to.shared.u64 t, %1; cvt.u32.u64 %0, t; }"
        : "=r"(a) : "l"(p));
    return a;
}
// 128B-row tiles: XOR 16B-chunk by (row&7)
__device__ __forceinline__ uint32_t swz_addr(uint32_t base, int row, int chunk) {
    uint32_t off = (uint32_t)(row * 128 + chunk * 16);
    return base + (off ^ ((off >> 3) & 0x70));
}
// 64B-row tiles: SW64 swizzle
__device__ __forceinline__ uint32_t swz64_addr(uint32_t base, int row, int chunk) {
    uint32_t off = (uint32_t)(row * 64 + chunk * 16);
    return base + (off ^ ((off >> 3) & 0x30));
}
__device__ __forceinline__ void ldsm_x4(uint32_t* r, uint32_t a) {
    asm volatile("ldmatrix.sync.aligned.m8n8.x4.shared.b16 {%0,%1,%2,%3}, [%4];"
        : "=r"(r[0]), "=r"(r[1]), "=r"(r[2]), "=r"(r[3]) : "r"(a));
}
__device__ __forceinline__ void ldsm_x4t(uint32_t* r, uint32_t a) {
    asm volatile("ldmatrix.sync.aligned.m8n8.x4.trans.shared.b16 {%0,%1,%2,%3}, [%4];"
        : "=r"(r[0]), "=r"(r[1]), "=r"(r[2]), "=r"(r[3]) : "r"(a));
}
__device__ __forceinline__ void mma_bf16(float* d, const uint32_t* a,
                                         uint32_t b0, uint32_t b1) {
    asm volatile("mma.sync.aligned.m16n8k16.row.col.f32.bf16.bf16.f32 "
        "{%0,%1,%2,%3}, {%4,%5,%6,%7}, {%8,%9}, {%0,%1,%2,%3};"
        : "+f"(d[0]), "+f"(d[1]), "+f"(d[2]), "+f"(d[3])
        : "r"(a[0]), "r"(a[1]), "r"(a[2]), "r"(a[3]), "r"(b0), "r"(b1));
}
__device__ __forceinline__ void mma_f16(float* d, const uint32_t* a,
                                        uint32_t b0, uint32_t b1) {
    asm volatile("mma.sync.aligned.m16n8k16.row.col.f32.f16.f16.f32 "
        "{%0,%1,%2,%3}, {%4,%5,%6,%7}, {%8,%9}, {%0,%1,%2,%3};"
        : "+f"(d[0]), "+f"(d[1]), "+f"(d[2]), "+f"(d[3])
        : "r"(a[0]), "r"(a[1]), "r"(a[2]), "r"(a[3]), "r"(b0), "r"(b1));
}
__device__ __forceinline__ void cp16(uint32_t dst, const void* src) {
    asm volatile("cp.async.cg.shared.global [%0], [%1], 16;"
                 :: "r"(dst), "l"(src) : "memory");
}
#define CP_COMMIT() asm volatile("cp.async.commit_group;" ::: "memory")
#define CP_WAIT1()  asm volatile("cp.async.wait_group 1;" ::: "memory")

// ---------------------------------------------------------------------------
// Kernel 0: split fp32 sources into hi/lo bf16 buffers (x, wq, wk, wv).
// ---------------------------------------------------------------------------
__global__ __launch_bounds__(256) void split_src_kernel(
    const float* __restrict__ x,
    const float* __restrict__ wq, const float* __restrict__ wk,
    const float* __restrict__ wv)
{
    const int z = blockIdx.y;
    const float* src;
    uint32_t *oh, *ol;
    size_t n2;
    if (z == 0) {
        src = x; oh = (uint32_t*)g_xh; ol = (uint32_t*)g_xl;
        n2 = (size_t)BSZ * SEQ * DM / 2;
    } else {
        src = (z == 1) ? wq : (z == 2) ? wk : wv;
        oh = (uint32_t*)(g_wh + (size_t)(z - 1) * DM * DM);
        ol = (uint32_t*)(g_wl + (size_t)(z - 1) * DM * DM);
        n2 = (size_t)DM * DM / 2;
    }
    for (size_t i = (size_t)blockIdx.x * 256 + threadIdx.x; i < n2;
         i += (size_t)gridDim.x * 256) {
        float2 v = ((const float2*)src)[i];
        uint32_t hi, lo;
        split2(v.x, v.y, hi, lo);
        oh[i] = hi; ol[i] = lo;
    }
}

// ---------------------------------------------------------------------------
// Kernel 1: QKV projection via HMMA bf16x3. 128x128 tile, K-slab 32,
// 64B-row smem (SW64 swizzle), double-buffered, 2 CTAs/SM.
// Q/K -> bf16 hi/lo; V -> single fp16.
// ---------------------------------------------------------------------------
#define QKV_SMEM_BYTES 65536

__global__ __launch_bounds__(256, 2) void qkv_hmma_kernel(
    const float* __restrict__ bq, const float* __restrict__ bk,
    const float* __restrict__ bv)
{
    extern __shared__ char smem[];
    const uint32_t sb = smem_u32(smem);
    const int tid = threadIdx.x, wid = tid >> 5, lane = tid & 31;
    const int z = blockIdx.z;
    const float* bvec = (z == 0) ? bq : (z == 1) ? bk : bv;
    __nv_bfloat16* ohi = (z == 0) ? g_q_hi : g_k_hi;
    __nv_bfloat16* olo = (z == 0) ? g_q_lo : g_k_lo;
    const __nv_bfloat16* WH = g_wh + (size_t)z * DM * DM;
    const __nv_bfloat16* WL = g_wl + (size_t)z * DM * DM;
    const int col0 = blockIdx.x << 7;
    const int row0 = blockIdx.y << 7;

    auto issue = [&](int slab, int buf) {
        const int k0 = slab << 5;
        const uint32_t base = sb + (uint32_t)buf * 32768;
        #pragma unroll
        for (int it = 0; it < 2; it++) {
            const int idx = tid + it * 256;     // 0..511
            const int r = idx >> 2, c = idx & 3;
            uint32_t off = (uint32_t)(r * 64 + c * 16);
            off ^= (off >> 3) & 0x30;
            const size_t gx = (size_t)(row0 + r) * DM + k0 + c * 8;
            const size_t gw = (size_t)(col0 + r) * DM + k0 + c * 8;
            cp16(base + off,         g_xh + gx);
            cp16(base + 8192 + off,  g_xl + gx);
            cp16(base + 16384 + off, WH + gw);
            cp16(base + 24576 + off, WL + gw);
        }
    };

    float s[16][4];
    #pragma unroll
    for (int g = 0; g < 16; g++)
        #pragma unroll
        for (int j = 0; j < 4; j++) s[g][j] = 0.0f;

    issue(0, 0);
    CP_COMMIT();

    for (int kt = 0; kt < 32; kt++) {
        if (kt) __syncthreads();
        if (kt < 31) issue(kt + 1, (kt + 1) & 1);
        CP_COMMIT();
        CP_WAIT1();
        __syncthreads();

        const uint32_t base = sb + (uint32_t)(kt & 1) * 32768;
        const int rA = (wid << 4) + (lane & 7) + ((lane >> 3) & 1) * 8;
        uint32_t ah[2][4], al[2][4];
        #pragma unroll
        for (int ks = 0; ks < 2; ks++) {
            const int ch = ks * 2 + (lane >> 4);
            ldsm_x4(ah[ks], swz64_addr(base,        rA, ch));
            ldsm_x4(al[ks], swz64_addr(base + 8192, rA, ch));
        }
        #pragma unroll
        for (int nf = 0; nf < 8; nf++) {
            const int rB = nf * 16 + (lane & 7) + (lane >> 4) * 8;
            #pragma unroll
            for (int ks = 0; ks < 2; ks++) {
                const int ch = ks * 2 + ((lane >> 3) & 1);
                uint32_t wh4[4], wl4[4];
                ldsm_x4(wh4, swz64_addr(base + 16384, rB, ch));
                ldsm_x4(wl4, swz64_addr(base + 24576, rB, ch));
                mma_bf16(s[2*nf],   ah[ks], wh4[0], wh4[1]);
                mma_bf16(s[2*nf+1], ah[ks], wh4[2], wh4[3]);
                mma_bf16(s[2*nf],   ah[ks], wl4[0], wl4[1]);
                mma_bf16(s[2*nf+1], ah[ks], wl4[2], wl4[3]);
                mma_bf16(s[2*nf],   al[ks], wh4[0], wh4[1]);
                mma_bf16(s[2*nf+1], al[ks], wh4[2], wh4[3]);
            }
        }
    }

    // epilogue: + bias; Q/K -> split bf16 hi/lo, V -> fp16 single
    const int r1 = row0 + (wid << 4) + (lane >> 2);
    const int r2 = r1 + 8;
    const int bb1 = r1 >> 11, ss1 = r1 & (SEQ - 1);
    const int bb2 = r2 >> 11, ss2 = r2 & (SEQ - 1);
    if (z == 2) {
        #pragma unroll
        for (int g = 0; g < 16; g++) {
            const int c = col0 + g * 8 + (lane & 3) * 2;
            const int h = c >> 6, d = c & 63;
            float2 b2 = *(const float2*)(bvec + c);
            __half2 v1 = __floats2half2_rn(s[g][0] + b2.x, s[g][1] + b2.y);
            __half2 v2 = __floats2half2_rn(s[g][2] + b2.x, s[g][3] + b2.y);
            const size_t e1 = (((size_t)bb1 * NH + h) * SEQ + ss1) * HD + d;
            const size_t e2 = (((size_t)bb2 * NH + h) * SEQ + ss2) * HD + d;
            *(__half2*)&g_vh[e1] = v1;
            *(__half2*)&g_vh[e2] = v2;
        }
    } else {
        #pragma unroll
        for (int g = 0; g < 16; g++) {
            const int c = col0 + g * 8 + (lane & 3) * 2;
            const int h = c >> 6, d = c & 63;
            float2 b2 = *(const float2*)(bvec + c);
            uint32_t hi, lo;
            split2(s[g][0] + b2.x, s[g][1] + b2.y, hi, lo);
            const size_t e1 = (((size_t)bb1 * NH + h) * SEQ + ss1) * HD + d;
            *(uint32_t*)&ohi[e1] = hi; *(uint32_t*)&olo[e1] = lo;
            split2(s[g][2] + b2.x, s[g][3] + b2.y, hi, lo);
            const size_t e2 = (((size_t)bb2 * NH + h) * SEQ + ss2) * HD + d;
            *(uint32_t*)&ohi[e2] = hi; *(uint32_t*)&olo[e2] = lo;
        }
    }
}

// ---------------------------------------------------------------------------
// Kernel 2: HMMA attention. S = QK^T bf16x3; PV = fp16 2-term (Ph·V + Pl·V).
// 64-wide k-tiles, 2 CTAs/SM, fused attn rescale.
// ---------------------------------------------------------------------------
#define SM_QH 0
#define SM_QL 16384
#define SM_TILES 32768                 // + buf*24576: KH+0, KL+8K, VH+16K
#define ATTN_SMEM_BYTES (32768 + 2*24576)

__global__ __launch_bounds__(256, 2) void attn_mma_kernel(
    const float* __restrict__ bias,
    const int*   __restrict__ mask,
    float* __restrict__ outp,
    float* __restrict__ attn)
{
    extern __shared__ char smem[];
    const uint32_t sb = smem_u32(smem);

    const int tid = threadIdx.x;
    const int wid = tid >> 5, lane = tid & 31;
    const int bh = blockIdx.y;
    const int h  = bh & (NH - 1);
    const int q0 = blockIdx.x << 7;
    const float scale = 0.125f;
    const float PS = 0.0625f;          // P pre-scale (fp16 overflow headroom)
    const size_t bhbase = (size_t)bh * SEQ;

    auto issue_kv = [&](int kt, int buf) {
        const int k0 = kt << 6;
        const uint32_t base = sb + SM_TILES + (uint32_t)buf * 24576;
        const char* kh = (const char*)(g_k_hi + (bhbase + k0) * HD);
        const char* kl = (const char*)(g_k_lo + (bhbase + k0) * HD);
        const char* vh = (const char*)(g_vh   + (bhbase + k0) * HD);
        #pragma unroll
        for (int it = 0; it < 2; it++) {
            const int idx = tid + it * 256;     // 0..511
            const uint32_t off = (uint32_t)(idx << 4);
            const uint32_t dst = off ^ ((off >> 3) & 0x70);
            cp16(base + dst,         kh + off);
            cp16(base + 8192 + dst,  kl + off);
            cp16(base + 16384 + dst, vh + off);
        }
    };

    // prologue: Q tiles + K/V(0)
    {
        const char* qh = (const char*)(g_q_hi + (bhbase + q0) * HD);
        const char* ql = (const char*)(g_q_lo + (bhbase + q0) * HD);
        #pragma unroll
        for (int it = 0; it < 4; it++) {
            const int idx = tid + it * 256;     // 0..1023
            const uint32_t off = (uint32_t)(idx << 4);
            const uint32_t dst = off ^ ((off >> 3) & 0x70);
            cp16(sb + SM_QH + dst, qh + off);
            cp16(sb + SM_QL + dst, ql + off);
        }
    }
    issue_kv(0, 0);
    CP_COMMIT();

    float o[8][4];
    #pragma unroll
    for (int g = 0; g < 8; g++)
        #pragma unroll
        for (int j = 0; j < 4; j++) o[g][j] = 0.0f;
    float rsum1 = 0.0f, rsum2 = 0.0f;

    const int r1 = (wid << 4) + (lane >> 2);
    const int qg1 = q0 + r1, qg2 = qg1 + 8;
    const float* brow1 = bias + ((size_t)h * SEQ + qg1) * SEQ;
    const float* brow2 = bias + ((size_t)h * SEQ + qg2) * SEQ;
    const int*   mrow1 = mask + (size_t)qg1 * SEQ;
    const int*   mrow2 = mask + (size_t)qg2 * SEQ;
    float*       arow1 = attn + (bhbase + qg1) * SEQ;
    float*       arow2 = attn + (bhbase + qg2) * SEQ;

    const int rA = (wid << 4) + (lane & 7) + ((lane >> 3) & 1) * 8;

    for (int kt = 0; kt < SEQ / 64; kt++) {
        const int k0 = kt << 6;
        if (kt) __syncthreads();
        if (kt < SEQ / 64 - 1) issue_kv(kt + 1, (kt + 1) & 1);
        CP_COMMIT();
        CP_WAIT1();
        __syncthreads();

        const uint32_t base = sb + SM_TILES + (uint32_t)(kt & 1) * 24576;

        // ---- S = Q K^T over 64 cols (8 n8-groups), bf16x3 ----
        float s[8][4];
        #pragma unroll
        for (int g = 0; g < 8; g++)
            #pragma unroll
            for (int j = 0; j < 4; j++) s[g][j] = 0.0f;

        #pragma unroll
        for (int ks = 0; ks < 4; ks++) {
            uint32_t qfh[4], qfl[4];
            const int chA = ks * 2 + (lane >> 4);
            ldsm_x4(qfh, swz_addr(sb + SM_QH, rA, chA));
            ldsm_x4(qfl, swz_addr(sb + SM_QL, rA, chA));
            #pragma unroll
            for (int nf = 0; nf < 4; nf++) {
                const int rB = nf * 16 + (lane & 7) + (lane >> 4) * 8;
                const int ch = ks * 2 + ((lane >> 3) & 1);
                uint32_t kh4[4], kl4[4];
                ldsm_x4(kh4, swz_addr(base,        rB, ch));
                ldsm_x4(kl4, swz_addr(base + 8192, rB, ch));
                mma_bf16(s[2*nf],   qfh, kh4[0], kh4[1]);
                mma_bf16(s[2*nf+1], qfh, kh4[2], kh4[3]);
                mma_bf16(s[2*nf],   qfh, kl4[0], kl4[1]);
                mma_bf16(s[2*nf+1], qfh, kl4[2], kl4[3]);
                mma_bf16(s[2*nf],   qfl, kh4[0], kh4[1]);
                mma_bf16(s[2*nf+1], qfl, kh4[2], kh4[3]);
            }
        }

        // ---- register epilogue: bias + mask + exp; attn store; pack P fp16 --
        uint32_t ph[4][4], pl[4][4];
        #pragma unroll
        for (int g = 0; g < 8; g++) {
            const int c = k0 + g * 8 + (lane & 3) * 2;
            float2 bA = *(const float2*)(brow1 + c);
            float2 bB = *(const float2*)(brow2 + c);
            int2   mA = *(const int2*)(mrow1 + c);
            int2   mB = *(const int2*)(mrow2 + c);
            float p0 = mA.x ? __expf(fmaf(s[g][0], scale, bA.x)) : 0.0f;
            float p1 = mA.y ? __expf(fmaf(s[g][1], scale, bA.y)) : 0.0f;
            float p2 = mB.x ? __expf(fmaf(s[g][2], scale, bB.x)) : 0.0f;
            float p3 = mB.y ? __expf(fmaf(s[g][3], scale, bB.y)) : 0.0f;
            rsum1 += p0 + p1;
            rsum2 += p2 + p3;
            *(float2*)(arow1 + c) = make_float2(p0, p1);
            *(float2*)(arow2 + c) = make_float2(p2, p3);
            const int ks = g >> 1, ix = (g & 1) * 2;
            split2h(p0 * PS, p1 * PS, ph[ks][ix + 0], pl[ks][ix + 0]);
            split2h(p2 * PS, p3 * PS, ph[ks][ix + 1], pl[ks][ix + 1]);
        }

        // ---- O += P V (fp16 2-term): B = V via ldmatrix.trans ----
        #pragma unroll
        for (int ks = 0; ks < 4; ks++) {
            const int rV = ks * 16 + (lane & 7) + ((lane >> 3) & 1) * 8;
            #pragma unroll
            for (int dg = 0; dg < 4; dg++) {
                const int ch = 2 * dg + (lane >> 4);
                uint32_t vh4[4];
                ldsm_x4t(vh4, swz_addr(base + 16384, rV, ch));
                mma_f16(o[2*dg],   ph[ks], vh4[0], vh4[1]);
                mma_f16(o[2*dg+1], ph[ks], vh4[2], vh4[3]);
                mma_f16(o[2*dg],   pl[ks], vh4[0], vh4[1]);
                mma_f16(o[2*dg+1], pl[ks], vh4[2], vh4[3]);
            }
        }
    }

    // ---- rowsum quad-reduce ----
    rsum1 += __shfl_xor_sync(0xffffffffu, rsum1, 1);
    rsum1 += __shfl_xor_sync(0xffffffffu, rsum1, 2);
    rsum2 += __shfl_xor_sync(0xffffffffu, rsum2, 1);
    rsum2 += __shfl_xor_sync(0xffffffffu, rsum2, 2);
    const float inv1 = 1.0f / rsum1;
    const float inv2 = 1.0f / rsum2;

    // normalized O (undo the PS pre-scale: O_acc = PS * P·V)
    const float inv1o = inv1 * (1.0f / PS);
    const float inv2o = inv2 * (1.0f / PS);
    float* or1 = outp + (bhbase + qg1) * HD;
    float* or2 = outp + (bhbase + qg2) * HD;
    #pragma unroll
    for (int g = 0; g < 8; g++) {
        const int c = g * 8 + (lane & 3) * 2;
        *(float2*)(or1 + c) = make_float2(o[g][0] * inv1o, o[g][1] * inv1o);
        *(float2*)(or2 + c) = make_float2(o[g][2] * inv2o, o[g][3] * inv2o);
    }

    // ---- fused attn rescale: warp rescales its own 16 rows ----
    float* rs = (float*)smem;          // 128 floats; KV smem no longer needed
    __syncthreads();                   // all attn stores done; smem free
    if ((lane & 3) == 0) {
        rs[r1] = inv1;
        rs[qg2 - q0] = inv2;
    }
    __syncthreads();
    #pragma unroll 1
    for (int rr = 0; rr < 16; rr++) {
        const int qr = (wid << 4) + rr;
        const float inv = rs[qr];
        float4* row = (float4*)(attn + (bhbase + q0 + qr) * SEQ);
        #pragma unroll 4
        for (int c = lane; c < SEQ / 4; c += 32) {
            float4 v = row[c];
            v.x *= inv; v.y *= inv; v.z *= inv; v.w *= inv;
            row[c] = v;
        }
    }
}

// ---------------------------------------------------------------------------
extern "C" void kernel_launch(void* const* d_in, const int* in_sizes, int n_in,
                              void* d_out, int out_size)
{
    const float* x    = (const float*)d_in[0];
    const float* bias = (const float*)d_in[1];
    const int*   mask = (const int*)d_in[2];
    const float* wq   = (const float*)d_in[3];
    const float* bq   = (const float*)d_in[4];
    const float* wk   = (const float*)d_in[5];
    const float* bk   = (const float*)d_in[6];
    const float* wv   = (const float*)d_in[7];
    const float* bv   = (const float*)d_in[8];

    float* outp = (float*)d_out;                       // [2,16,2048,64]
    float* attn = outp + (size_t)BH * SEQ * HD;        // [2,16,2048,2048]

    cudaFuncSetAttribute(qkv_hmma_kernel,
                         cudaFuncAttributeMaxDynamicSharedMemorySize,
                         QKV_SMEM_BYTES);
    cudaFuncSetAttribute(attn_mma_kernel,
                         cudaFuncAttributeMaxDynamicSharedMemorySize,
                         ATTN_SMEM_BYTES);

    // 0) split x / W into hi+lo bf16
    split_src_kernel<<<dim3(2048, 4), 256>>>(x, wq, wk, wv);

    // 1) QKV projections (HMMA bf16x3) -> Q/K split-bf16, V fp16
    qkv_hmma_kernel<<<dim3(DM / 128, (BSZ * SEQ) / 128, 3), 256,
                      QKV_SMEM_BYTES>>>(bq, bk, bv);

    // 2) HMMA fused attention + fused rescale
    attn_mma_kernel<<<dim3(SEQ / 128, BH), 256, ATTN_SMEM_BYTES>>>(
        bias, mask, outp, attn);
}

// round 10
// speedup vs baseline: 1.2708x; 1.1776x over previous
#include <cuda_runtime.h>
#include <cuda_fp16.h>
#include <cstdint>

#define BSZ 2
#define NH 16
#define SEQ 2048
#define DM 1024
#define HD 64
#define BH (BSZ*NH)

// Scratch (device globals — no allocations allowed)
__device__ __half g_xh[BSZ*SEQ*DM];     // x hi (fp16)
__device__ __half g_xl[BSZ*SEQ*DM];     // x residual (fp16)
__device__ __half g_w16[3*DM*DM];       // W single fp16
__device__ __half g_q16[BH * SEQ * HD];
__device__ __half g_k16[BH * SEQ * HD];
__device__ __half g_v16[BH * SEQ * HD];

// ---- fp16 split helpers ------------------------------------------------------
__device__ __forceinline__ uint32_t h2bits(__half2 v) {
    return *reinterpret_cast<uint32_t*>(&v);
}
__device__ __forceinline__ void split2h(float a, float b, uint32_t& hi, uint32_t& lo) {
    __half2 h = __floats2half2_rn(a, b);
    float2 hf = __half22float2(h);
    __half2 l = __floats2half2_rn(a - hf.x, b - hf.y);
    hi = h2bits(h); lo = h2bits(l);
}

// ---- smem / ldmatrix / mma / cp.async primitives ----------------------------
__device__ __forceinline__ uint32_t smem_u32(const void* p) {
    uint32_t a;
    asm("{ .reg .u64 t; cvta.to.shared.u64 t, %1; cvt.u32.u64 %0, t; }"
        : "=r"(a) : "l"(p));
    return a;
}
// 128B-row tiles: XOR 16B-chunk by (row&7)
__device__ __forceinline__ uint32_t swz_addr(uint32_t base, int row, int chunk) {
    uint32_t off = (uint32_t)(row * 128 + chunk * 16);
    return base + (off ^ ((off >> 3) & 0x70));
}
// 64B-row tiles: SW64 swizzle
__device__ __forceinline__ uint32_t swz64_addr(uint32_t base, int row, int chunk) {
    uint32_t off = (uint32_t)(row * 64 + chunk * 16);
    return base + (off ^ ((off >> 3) & 0x30));
}
__device__ __forceinline__ void ldsm_x4(uint32_t* r, uint32_t a) {
    asm volatile("ldmatrix.sync.aligned.m8n8.x4.shared.b16 {%0,%1,%2,%3}, [%4];"
        : "=r"(r[0]), "=r"(r[1]), "=r"(r[2]), "=r"(r[3]) : "r"(a));
}
__device__ __forceinline__ void ldsm_x4t(uint32_t* r, uint32_t a) {
    asm volatile("ldmatrix.sync.aligned.m8n8.x4.trans.shared.b16 {%0,%1,%2,%3}, [%4];"
        : "=r"(r[0]), "=r"(r[1]), "=r"(r[2]), "=r"(r[3]) : "r"(a));
}
__device__ __forceinline__ void mma_f16(float* d, const uint32_t* a,
                                        uint32_t b0, uint32_t b1) {
    asm volatile("mma.sync.aligned.m16n8k16.row.col.f32.f16.f16.f32 "
        "{%0,%1,%2,%3}, {%4,%5,%6,%7}, {%8,%9}, {%0,%1,%2,%3};"
        : "+f"(d[0]), "+f"(d[1]), "+f"(d[2]), "+f"(d[3])
        : "r"(a[0]), "r"(a[1]), "r"(a[2]), "r"(a[3]), "r"(b0), "r"(b1));
}
__device__ __forceinline__ void cp16(uint32_t dst, const void* src) {
    asm volatile("cp.async.cg.shared.global [%0], [%1], 16;"
                 :: "r"(dst), "l"(src) : "memory");
}
#define CP_COMMIT() asm volatile("cp.async.commit_group;" ::: "memory")
#define CP_WAIT1()  asm volatile("cp.async.wait_group 1;" ::: "memory")

// ---------------------------------------------------------------------------
// Kernel 0: split x into fp16 hi/lo; round W to single fp16.
// ---------------------------------------------------------------------------
__global__ __launch_bounds__(256) void split_src_kernel(
    const float* __restrict__ x,
    const float* __restrict__ wq, const float* __restrict__ wk,
    const float* __restrict__ wv)
{
    const int z = blockIdx.y;
    if (z == 0) {
        uint32_t* oh = (uint32_t*)g_xh;
        uint32_t* ol = (uint32_t*)g_xl;
        const size_t n2 = (size_t)BSZ * SEQ * DM / 2;
        for (size_t i = (size_t)blockIdx.x * 256 + threadIdx.x; i < n2;
             i += (size_t)gridDim.x * 256) {
            float2 v = ((const float2*)x)[i];
            uint32_t hi, lo;
            split2h(v.x, v.y, hi, lo);
            oh[i] = hi; ol[i] = lo;
        }
    } else {
        const float* src = (z == 1) ? wq : (z == 2) ? wk : wv;
        uint32_t* ow = (uint32_t*)(g_w16 + (size_t)(z - 1) * DM * DM);
        const size_t n2 = (size_t)DM * DM / 2;
        for (size_t i = (size_t)blockIdx.x * 256 + threadIdx.x; i < n2;
             i += (size_t)gridDim.x * 256) {
            float2 v = ((const float2*)src)[i];
            ow[i] = h2bits(__floats2half2_rn(v.x, v.y));
        }
    }
}

// ---------------------------------------------------------------------------
// Kernel 1: QKV projection via 2-term fp16 HMMA (xh*W + xl*W; W fp16-exact).
// 128x128 tile, K-slab 32, 64B-row smem (SW64), double-buffered, 2 CTAs/SM.
// ---------------------------------------------------------------------------
#define QKV_SMEM_BYTES 49152     // 2 stages x (xh 8K | xl 8K | w 8K)

__global__ __launch_bounds__(256, 2) void qkv_hmma_kernel(
    const float* __restrict__ bq, const float* __restrict__ bk,
    const float* __restrict__ bv)
{
    extern __shared__ char smem[];
    const uint32_t sb = smem_u32(smem);
    const int tid = threadIdx.x, wid = tid >> 5, lane = tid & 31;
    const int z = blockIdx.z;
    const float* bvec = (z == 0) ? bq : (z == 1) ? bk : bv;
    __half* outp = (z == 0) ? g_q16 : (z == 1) ? g_k16 : g_v16;
    const __half* W = g_w16 + (size_t)z * DM * DM;
    const int col0 = blockIdx.x << 7;
    const int row0 = blockIdx.y << 7;

    auto issue = [&](int slab, int buf) {
        const int k0 = slab << 5;
        const uint32_t base = sb + (uint32_t)buf * 24576;
        #pragma unroll
        for (int it = 0; it < 2; it++) {
            const int idx = tid + it * 256;     // 0..511
            const int r = idx >> 2, c = idx & 3;
            uint32_t off = (uint32_t)(r * 64 + c * 16);
            off ^= (off >> 3) & 0x30;
            const size_t gx = (size_t)(row0 + r) * DM + k0 + c * 8;
            const size_t gw = (size_t)(col0 + r) * DM + k0 + c * 8;
            cp16(base + off,         g_xh + gx);
            cp16(base + 8192 + off,  g_xl + gx);
            cp16(base + 16384 + off, W + gw);
        }
    };

    float s[16][4];
    #pragma unroll
    for (int g = 0; g < 16; g++)
        #pragma unroll
        for (int j = 0; j < 4; j++) s[g][j] = 0.0f;

    issue(0, 0);
    CP_COMMIT();

    for (int kt = 0; kt < 32; kt++) {
        if (kt) __syncthreads();
        if (kt < 31) issue(kt + 1, (kt + 1) & 1);
        CP_COMMIT();
        CP_WAIT1();
        __syncthreads();

        const uint32_t base = sb + (uint32_t)(kt & 1) * 24576;
        const int rA = (wid << 4) + (lane & 7) + ((lane >> 3) & 1) * 8;
        uint32_t ah[2][4], al[2][4];
        #pragma unroll
        for (int ks = 0; ks < 2; ks++) {
            const int ch = ks * 2 + (lane >> 4);
            ldsm_x4(ah[ks], swz64_addr(base,        rA, ch));
            ldsm_x4(al[ks], swz64_addr(base + 8192, rA, ch));
        }
        #pragma unroll
        for (int nf = 0; nf < 8; nf++) {
            const int rB = nf * 16 + (lane & 7) + (lane >> 4) * 8;
            #pragma unroll
            for (int ks = 0; ks < 2; ks++) {
                const int ch = ks * 2 + ((lane >> 3) & 1);
                uint32_t w4[4];
                ldsm_x4(w4, swz64_addr(base + 16384, rB, ch));
                mma_f16(s[2*nf],   ah[ks], w4[0], w4[1]);
                mma_f16(s[2*nf+1], ah[ks], w4[2], w4[3]);
                mma_f16(s[2*nf],   al[ks], w4[0], w4[1]);
                mma_f16(s[2*nf+1], al[ks], w4[2], w4[3]);
            }
        }
    }

    // epilogue: + bias; store single fp16, head-split
    const int r1 = row0 + (wid << 4) + (lane >> 2);
    const int r2 = r1 + 8;
    const int bb1 = r1 >> 11, ss1 = r1 & (SEQ - 1);
    const int bb2 = r2 >> 11, ss2 = r2 & (SEQ - 1);
    #pragma unroll
    for (int g = 0; g < 16; g++) {
        const int c = col0 + g * 8 + (lane & 3) * 2;
        const int h = c >> 6, d = c & 63;
        float2 b2 = *(const float2*)(bvec + c);
        const size_t e1 = (((size_t)bb1 * NH + h) * SEQ + ss1) * HD + d;
        const size_t e2 = (((size_t)bb2 * NH + h) * SEQ + ss2) * HD + d;
        *(uint32_t*)&outp[e1] = h2bits(__floats2half2_rn(s[g][0] + b2.x, s[g][1] + b2.y));
        *(uint32_t*)&outp[e2] = h2bits(__floats2half2_rn(s[g][2] + b2.x, s[g][3] + b2.y));
    }
}

// ---------------------------------------------------------------------------
// Kernel 2: fp16 HMMA attention. S = Q K^T (1 term); PV = P V (1 term).
// 64-wide k-tiles, 2 CTAs/SM, fused attn rescale.
// ---------------------------------------------------------------------------
#define SM_Q 0
#define SM_TILES 16384                 // + buf*16384: K @0, V @8192
#define ATTN_SMEM_BYTES (16384 + 2*16384)

__global__ __launch_bounds__(256, 2) void attn_mma_kernel(
    const float* __restrict__ bias,
    const int*   __restrict__ mask,
    float* __restrict__ outp,
    float* __restrict__ attn)
{
    extern __shared__ char smem[];
    const uint32_t sb = smem_u32(smem);

    const int tid = threadIdx.x;
    const int wid = tid >> 5, lane = tid & 31;
    const int bh = blockIdx.y;
    const int h  = bh & (NH - 1);
    const int q0 = blockIdx.x << 7;
    const float scale = 0.125f;
    const float PS = 0.0625f;          // P pre-scale (fp16 headroom)
    const size_t bhbase = (size_t)bh * SEQ;

    auto issue_kv = [&](int kt, int buf) {
        const int k0 = kt << 6;
        const uint32_t base = sb + SM_TILES + (uint32_t)buf * 16384;
        const char* kk = (const char*)(g_k16 + (bhbase + k0) * HD);
        const char* vv = (const char*)(g_v16 + (bhbase + k0) * HD);
        #pragma unroll
        for (int it = 0; it < 2; it++) {
            const int idx = tid + it * 256;     // 0..511
            const uint32_t off = (uint32_t)(idx << 4);
            const uint32_t dst = off ^ ((off >> 3) & 0x70);
            cp16(base + dst,        kk + off);
            cp16(base + 8192 + dst, vv + off);
        }
    };

    // prologue: Q tile (128x64 fp16 = 16KB) + K/V(0)
    {
        const char* qq = (const char*)(g_q16 + (bhbase + q0) * HD);
        #pragma unroll
        for (int it = 0; it < 4; it++) {
            const int idx = tid + it * 256;     // 0..1023
            const uint32_t off = (uint32_t)(idx << 4);
            const uint32_t dst = off ^ ((off >> 3) & 0x70);
            cp16(sb + SM_Q + dst, qq + off);
        }
    }
    issue_kv(0, 0);
    CP_COMMIT();

    float o[8][4];
    #pragma unroll
    for (int g = 0; g < 8; g++)
        #pragma unroll
        for (int j = 0; j < 4; j++) o[g][j] = 0.0f;
    float rsum1 = 0.0f, rsum2 = 0.0f;

    const int r1 = (wid << 4) + (lane >> 2);
    const int qg1 = q0 + r1, qg2 = qg1 + 8;
    const float* brow1 = bias + ((size_t)h * SEQ + qg1) * SEQ;
    const float* brow2 = bias + ((size_t)h * SEQ + qg2) * SEQ;
    const int*   mrow1 = mask + (size_t)qg1 * SEQ;
    const int*   mrow2 = mask + (size_t)qg2 * SEQ;
    float*       arow1 = attn + (bhbase + qg1) * SEQ;
    float*       arow2 = attn + (bhbase + qg2) * SEQ;

    const int rA = (wid << 4) + (lane & 7) + ((lane >> 3) & 1) * 8;

    for (int kt = 0; kt < SEQ / 64; kt++) {
        const int k0 = kt << 6;
        if (kt) __syncthreads();
        if (kt < SEQ / 64 - 1) issue_kv(kt + 1, (kt + 1) & 1);
        CP_COMMIT();
        CP_WAIT1();
        __syncthreads();

        const uint32_t base = sb + SM_TILES + (uint32_t)(kt & 1) * 16384;

        // ---- S = Q K^T over 64 cols (8 n8-groups), single fp16 term ----
        float s[8][4];
        #pragma unroll
        for (int g = 0; g < 8; g++)
            #pragma unroll
            for (int j = 0; j < 4; j++) s[g][j] = 0.0f;

        #pragma unroll
        for (int ks = 0; ks < 4; ks++) {
            uint32_t qf[4];
            const int chA = ks * 2 + (lane >> 4);
            ldsm_x4(qf, swz_addr(sb + SM_Q, rA, chA));
            #pragma unroll
            for (int nf = 0; nf < 4; nf++) {
                const int rB = nf * 16 + (lane & 7) + (lane >> 4) * 8;
                const int ch = ks * 2 + ((lane >> 3) & 1);
                uint32_t k4[4];
                ldsm_x4(k4, swz_addr(base, rB, ch));
                mma_f16(s[2*nf],   qf, k4[0], k4[1]);
                mma_f16(s[2*nf+1], qf, k4[2], k4[3]);
            }
        }

        // ---- register epilogue: bias + mask + exp; attn store; pack P fp16 --
        uint32_t ph[4][4];
        #pragma unroll
        for (int g = 0; g < 8; g++) {
            const int c = k0 + g * 8 + (lane & 3) * 2;
            float2 bA = *(const float2*)(brow1 + c);
            float2 bB = *(const float2*)(brow2 + c);
            int2   mA = *(const int2*)(mrow1 + c);
            int2   mB = *(const int2*)(mrow2 + c);
            float p0 = mA.x ? __expf(fmaf(s[g][0], scale, bA.x)) : 0.0f;
            float p1 = mA.y ? __expf(fmaf(s[g][1], scale, bA.y)) : 0.0f;
            float p2 = mB.x ? __expf(fmaf(s[g][2], scale, bB.x)) : 0.0f;
            float p3 = mB.y ? __expf(fmaf(s[g][3], scale, bB.y)) : 0.0f;
            rsum1 += p0 + p1;
            rsum2 += p2 + p3;
            *(float2*)(arow1 + c) = make_float2(p0, p1);
            *(float2*)(arow2 + c) = make_float2(p2, p3);
            const int ks = g >> 1, ix = (g & 1) * 2;
            ph[ks][ix + 0] = h2bits(__floats2half2_rn(p0 * PS, p1 * PS));
            ph[ks][ix + 1] = h2bits(__floats2half2_rn(p2 * PS, p3 * PS));
        }

        // ---- O += P V (single fp16 term): B = V via ldmatrix.trans ----
        #pragma unroll
        for (int ks = 0; ks < 4; ks++) {
            const int rV = ks * 16 + (lane & 7) + ((lane >> 3) & 1) * 8;
            #pragma unroll
            for (int dg = 0; dg < 4; dg++) {
                const int ch = 2 * dg + (lane >> 4);
                uint32_t v4[4];
                ldsm_x4t(v4, swz_addr(base + 8192, rV, ch));
                mma_f16(o[2*dg],   ph[ks], v4[0], v4[1]);
                mma_f16(o[2*dg+1], ph[ks], v4[2], v4[3]);
            }
        }
    }

    // ---- rowsum quad-reduce ----
    rsum1 += __shfl_xor_sync(0xffffffffu, rsum1, 1);
    rsum1 += __shfl_xor_sync(0xffffffffu, rsum1, 2);
    rsum2 += __shfl_xor_sync(0xffffffffu, rsum2, 1);
    rsum2 += __shfl_xor_sync(0xffffffffu, rsum2, 2);
    const float inv1 = 1.0f / rsum1;
    const float inv2 = 1.0f / rsum2;

    // normalized O (undo PS)
    const float inv1o = inv1 * (1.0f / PS);
    const float inv2o = inv2 * (1.0f / PS);
    float* or1 = outp + (bhbase + qg1) * HD;
    float* or2 = outp + (bhbase + qg2) * HD;
    #pragma unroll
    for (int g = 0; g < 8; g++) {
        const int c = g * 8 + (lane & 3) * 2;
        *(float2*)(or1 + c) = make_float2(o[g][0] * inv1o, o[g][1] * inv1o);
        *(float2*)(or2 + c) = make_float2(o[g][2] * inv2o, o[g][3] * inv2o);
    }

    // ---- fused attn rescale: warp rescales its own 16 rows ----
    float* rs = (float*)smem;          // 128 floats; KV smem no longer needed
    __syncthreads();                   // all attn stores done; smem free
    if ((lane & 3) == 0) {
        rs[r1] = inv1;
        rs[qg2 - q0] = inv2;
    }
    __syncthreads();
    #pragma unroll 1
    for (int rr = 0; rr < 16; rr++) {
        const int qr = (wid << 4) + rr;
        const float inv = rs[qr];
        float4* row = (float4*)(attn + (bhbase + q0 + qr) * SEQ);
        #pragma unroll 4
        for (int c = lane; c < SEQ / 4; c += 32) {
            float4 v = row[c];
            v.x *= inv; v.y *= inv; v.z *= inv; v.w *= inv;
            row[c] = v;
        }
    }
}

// ---------------------------------------------------------------------------
extern "C" void kernel_launch(void* const* d_in, const int* in_sizes, int n_in,
                              void* d_out, int out_size)
{
    const float* x    = (const float*)d_in[0];
    const float* bias = (const float*)d_in[1];
    const int*   mask = (const int*)d_in[2];
    const float* wq   = (const float*)d_in[3];
    const float* bq   = (const float*)d_in[4];
    const float* wk   = (const float*)d_in[5];
    const float* bk   = (const float*)d_in[6];
    const float* wv   = (const float*)d_in[7];
    const float* bv   = (const float*)d_in[8];

    float* outp = (float*)d_out;                       // [2,16,2048,64]
    float* attn = outp + (size_t)BH * SEQ * HD;        // [2,16,2048,2048]

    cudaFuncSetAttribute(qkv_hmma_kernel,
                         cudaFuncAttributeMaxDynamicSharedMemorySize,
                         QKV_SMEM_BYTES);
    cudaFuncSetAttribute(attn_mma_kernel,
                         cudaFuncAttributeMaxDynamicSharedMemorySize,
                         ATTN_SMEM_BYTES);

    // 0) split x to fp16 hi/lo; W to single fp16
    split_src_kernel<<<dim3(2048, 4), 256>>>(x, wq, wk, wv);

    // 1) QKV projections (fp16 2-term HMMA) -> fp16 Q/K/V
    qkv_hmma_kernel<<<dim3(DM / 128, (BSZ * SEQ) / 128, 3), 256,
                      QKV_SMEM_BYTES>>>(bq, bk, bv);

    // 2) fp16 HMMA fused attention + fused rescale
    attn_mma_kernel<<<dim3(SEQ / 128, BH), 256, ATTN_SMEM_BYTES>>>(
        bias, mask, outp, attn);
}

// round 11
// speedup vs baseline: 1.3245x; 1.0423x over previous
#include <cuda_runtime.h>
#include <cuda_fp16.h>
#include <cstdint>

#define BSZ 2
#define NH 16
#define SEQ 2048
#define DM 1024
#define HD 64
#define BH (BSZ*NH)

// Scratch (device globals — no allocations allowed)
__device__ __half g_xh[BSZ*SEQ*DM];     // x hi (fp16)
__device__ __half g_xl[BSZ*SEQ*DM];     // x residual (fp16)
__device__ __half g_w16[3*DM*DM];       // W single fp16
__device__ __half g_q16[BH * SEQ * HD];
__device__ __half g_k16[BH * SEQ * HD];
__device__ __half g_v16[BH * SEQ * HD];
__device__ __half g_p16[(size_t)BH * SEQ * SEQ];   // unnormalized P scratch (fp16)

// ---- fp16 split helpers ------------------------------------------------------
__device__ __forceinline__ uint32_t h2bits(__half2 v) {
    return *reinterpret_cast<uint32_t*>(&v);
}
__device__ __forceinline__ void split2h(float a, float b, uint32_t& hi, uint32_t& lo) {
    __half2 h = __floats2half2_rn(a, b);
    float2 hf = __half22float2(h);
    __half2 l = __floats2half2_rn(a - hf.x, b - hf.y);
    hi = h2bits(h); lo = h2bits(l);
}

// ---- smem / ldmatrix / mma / cp.async primitives ----------------------------
__device__ __forceinline__ uint32_t smem_u32(const void* p) {
    uint32_t a;
    asm("{ .reg .u64 t; cvta.to.shared.u64 t, %1; cvt.u32.u64 %0, t; }"
        : "=r"(a) : "l"(p));
    return a;
}
// 128B-row tiles: XOR 16B-chunk by (row&7)
__device__ __forceinline__ uint32_t swz_addr(uint32_t base, int row, int chunk) {
    uint32_t off = (uint32_t)(row * 128 + chunk * 16);
    return base + (off ^ ((off >> 3) & 0x70));
}
// 64B-row tiles: SW64 swizzle
__device__ __forceinline__ uint32_t swz64_addr(uint32_t base, int row, int chunk) {
    uint32_t off = (uint32_t)(row * 64 + chunk * 16);
    return base + (off ^ ((off >> 3) & 0x30));
}
__device__ __forceinline__ void ldsm_x4(uint32_t* r, uint32_t a) {
    asm volatile("ldmatrix.sync.aligned.m8n8.x4.shared.b16 {%0,%1,%2,%3}, [%4];"
        : "=r"(r[0]), "=r"(r[1]), "=r"(r[2]), "=r"(r[3]) : "r"(a));
}
__device__ __forceinline__ void ldsm_x4t(uint32_t* r, uint32_t a) {
    asm volatile("ldmatrix.sync.aligned.m8n8.x4.trans.shared.b16 {%0,%1,%2,%3}, [%4];"
        : "=r"(r[0]), "=r"(r[1]), "=r"(r[2]), "=r"(r[3]) : "r"(a));
}
__device__ __forceinline__ void mma_f16(float* d, const uint32_t* a,
                                        uint32_t b0, uint32_t b1) {
    asm volatile("mma.sync.aligned.m16n8k16.row.col.f32.f16.f16.f32 "
        "{%0,%1,%2,%3}, {%4,%5,%6,%7}, {%8,%9}, {%0,%1,%2,%3};"
        : "+f"(d[0]), "+f"(d[1]), "+f"(d[2]), "+f"(d[3])
        : "r"(a[0]), "r"(a[1]), "r"(a[2]), "r"(a[3]), "r"(b0), "r"(b1));
}
__device__ __forceinline__ void cp16(uint32_t dst, const void* src) {
    asm volatile("cp.async.cg.shared.global [%0], [%1], 16;"
                 :: "r"(dst), "l"(src) : "memory");
}
#define CP_COMMIT() asm volatile("cp.async.commit_group;" ::: "memory")
#define CP_WAIT1()  asm volatile("cp.async.wait_group 1;" ::: "memory")

// ---------------------------------------------------------------------------
// Kernel 0: split x into fp16 hi/lo; round W to single fp16.
// ---------------------------------------------------------------------------
__global__ __launch_bounds__(256) void split_src_kernel(
    const float* __restrict__ x,
    const float* __restrict__ wq, const float* __restrict__ wk,
    const float* __restrict__ wv)
{
    const int z = blockIdx.y;
    if (z == 0) {
        uint32_t* oh = (uint32_t*)g_xh;
        uint32_t* ol = (uint32_t*)g_xl;
        const size_t n2 = (size_t)BSZ * SEQ * DM / 2;
        for (size_t i = (size_t)blockIdx.x * 256 + threadIdx.x; i < n2;
             i += (size_t)gridDim.x * 256) {
            float2 v = ((const float2*)x)[i];
            uint32_t hi, lo;
            split2h(v.x, v.y, hi, lo);
            oh[i] = hi; ol[i] = lo;
        }
    } else {
        const float* src = (z == 1) ? wq : (z == 2) ? wk : wv;
        uint32_t* ow = (uint32_t*)(g_w16 + (size_t)(z - 1) * DM * DM);
        const size_t n2 = (size_t)DM * DM / 2;
        for (size_t i = (size_t)blockIdx.x * 256 + threadIdx.x; i < n2;
             i += (size_t)gridDim.x * 256) {
            float2 v = ((const float2*)src)[i];
            ow[i] = h2bits(__floats2half2_rn(v.x, v.y));
        }
    }
}

// ---------------------------------------------------------------------------
// Kernel 1: QKV projection via 2-term fp16 HMMA (xh*W + xl*W; W fp16-exact).
// 128x128 tile, K-slab 32, 64B-row smem (SW64), double-buffered, 2 CTAs/SM.
// ---------------------------------------------------------------------------
#define QKV_SMEM_BYTES 49152     // 2 stages x (xh 8K | xl 8K | w 8K)

__global__ __launch_bounds__(256, 2) void qkv_hmma_kernel(
    const float* __restrict__ bq, const float* __restrict__ bk,
    const float* __restrict__ bv)
{
    extern __shared__ char smem[];
    const uint32_t sb = smem_u32(smem);
    const int tid = threadIdx.x, wid = tid >> 5, lane = tid & 31;
    const int z = blockIdx.z;
    const float* bvec = (z == 0) ? bq : (z == 1) ? bk : bv;
    __half* outp = (z == 0) ? g_q16 : (z == 1) ? g_k16 : g_v16;
    const __half* W = g_w16 + (size_t)z * DM * DM;
    const int col0 = blockIdx.x << 7;
    const int row0 = blockIdx.y << 7;

    auto issue = [&](int slab, int buf) {
        const int k0 = slab << 5;
        const uint32_t base = sb + (uint32_t)buf * 24576;
        #pragma unroll
        for (int it = 0; it < 2; it++) {
            const int idx = tid + it * 256;     // 0..511
            const int r = idx >> 2, c = idx & 3;
            uint32_t off = (uint32_t)(r * 64 + c * 16);
            off ^= (off >> 3) & 0x30;
            const size_t gx = (size_t)(row0 + r) * DM + k0 + c * 8;
            const size_t gw = (size_t)(col0 + r) * DM + k0 + c * 8;
            cp16(base + off,         g_xh + gx);
            cp16(base + 8192 + off,  g_xl + gx);
            cp16(base + 16384 + off, W + gw);
        }
    };

    float s[16][4];
    #pragma unroll
    for (int g = 0; g < 16; g++)
        #pragma unroll
        for (int j = 0; j < 4; j++) s[g][j] = 0.0f;

    issue(0, 0);
    CP_COMMIT();

    for (int kt = 0; kt < 32; kt++) {
        if (kt) __syncthreads();
        if (kt < 31) issue(kt + 1, (kt + 1) & 1);
        CP_COMMIT();
        CP_WAIT1();
        __syncthreads();

        const uint32_t base = sb + (uint32_t)(kt & 1) * 24576;
        const int rA = (wid << 4) + (lane & 7) + ((lane >> 3) & 1) * 8;
        uint32_t ah[2][4], al[2][4];
        #pragma unroll
        for (int ks = 0; ks < 2; ks++) {
            const int ch = ks * 2 + (lane >> 4);
            ldsm_x4(ah[ks], swz64_addr(base,        rA, ch));
            ldsm_x4(al[ks], swz64_addr(base + 8192, rA, ch));
        }
        #pragma unroll
        for (int nf = 0; nf < 8; nf++) {
            const int rB = nf * 16 + (lane & 7) + (lane >> 4) * 8;
            #pragma unroll
            for (int ks = 0; ks < 2; ks++) {
                const int ch = ks * 2 + ((lane >> 3) & 1);
                uint32_t w4[4];
                ldsm_x4(w4, swz64_addr(base + 16384, rB, ch));
                mma_f16(s[2*nf],   ah[ks], w4[0], w4[1]);
                mma_f16(s[2*nf+1], ah[ks], w4[2], w4[3]);
                mma_f16(s[2*nf],   al[ks], w4[0], w4[1]);
                mma_f16(s[2*nf+1], al[ks], w4[2], w4[3]);
            }
        }
    }

    // epilogue: + bias; store single fp16, head-split
    const int r1 = row0 + (wid << 4) + (lane >> 2);
    const int r2 = r1 + 8;
    const int bb1 = r1 >> 11, ss1 = r1 & (SEQ - 1);
    const int bb2 = r2 >> 11, ss2 = r2 & (SEQ - 1);
    #pragma unroll
    for (int g = 0; g < 16; g++) {
        const int c = col0 + g * 8 + (lane & 3) * 2;
        const int h = c >> 6, d = c & 63;
        float2 b2 = *(const float2*)(bvec + c);
        const size_t e1 = (((size_t)bb1 * NH + h) * SEQ + ss1) * HD + d;
        const size_t e2 = (((size_t)bb2 * NH + h) * SEQ + ss2) * HD + d;
        *(uint32_t*)&outp[e1] = h2bits(__floats2half2_rn(s[g][0] + b2.x, s[g][1] + b2.y));
        *(uint32_t*)&outp[e2] = h2bits(__floats2half2_rn(s[g][2] + b2.x, s[g][3] + b2.y));
    }
}

// ---------------------------------------------------------------------------
// Kernel 2: fp16 HMMA attention. S = Q K^T; PV = P V. Unnormalized P written
// to fp16 scratch; fused rescale reads scratch and writes fp32 attn.
// blockIdx.y = h*2 + b so batch-pair CTAs share bias rows in L2.
// ---------------------------------------------------------------------------
#define SM_Q 0
#define SM_TILES 16384                 // + buf*16384: K @0, V @8192
#define ATTN_SMEM_BYTES (16384 + 2*16384)

__global__ __launch_bounds__(256, 2) void attn_mma_kernel(
    const float* __restrict__ bias,
    const int*   __restrict__ mask,
    float* __restrict__ outp,
    float* __restrict__ attn)
{
    extern __shared__ char smem[];
    const uint32_t sb = smem_u32(smem);

    const int tid = threadIdx.x;
    const int wid = tid >> 5, lane = tid & 31;
    const int h  = blockIdx.y >> 1;            // bias row set
    const int b  = blockIdx.y & 1;             // batch
    const int bh = b * NH + h;
    const int q0 = blockIdx.x << 7;
    const float scale = 0.125f;
    const float PS = 0.0625f;          // P pre-scale for PV fragments
    const size_t bhbase = (size_t)bh * SEQ;

    auto issue_kv = [&](int kt, int buf) {
        const int k0 = kt << 6;
        const uint32_t base = sb + SM_TILES + (uint32_t)buf * 16384;
        const char* kk = (const char*)(g_k16 + (bhbase + k0) * HD);
        const char* vv = (const char*)(g_v16 + (bhbase + k0) * HD);
        #pragma unroll
        for (int it = 0; it < 2; it++) {
            const int idx = tid + it * 256;     // 0..511
            const uint32_t off = (uint32_t)(idx << 4);
            const uint32_t dst = off ^ ((off >> 3) & 0x70);
            cp16(base + dst,        kk + off);
            cp16(base + 8192 + dst, vv + off);
        }
    };

    // prologue: Q tile (128x64 fp16 = 16KB) + K/V(0)
    {
        const char* qq = (const char*)(g_q16 + (bhbase + q0) * HD);
        #pragma unroll
        for (int it = 0; it < 4; it++) {
            const int idx = tid + it * 256;     // 0..1023
            const uint32_t off = (uint32_t)(idx << 4);
            const uint32_t dst = off ^ ((off >> 3) & 0x70);
            cp16(sb + SM_Q + dst, qq + off);
        }
    }
    issue_kv(0, 0);
    CP_COMMIT();

    float o[8][4];
    #pragma unroll
    for (int g = 0; g < 8; g++)
        #pragma unroll
        for (int j = 0; j < 4; j++) o[g][j] = 0.0f;
    float rsum1 = 0.0f, rsum2 = 0.0f;

    const int r1 = (wid << 4) + (lane >> 2);
    const int qg1 = q0 + r1, qg2 = qg1 + 8;
    const float* brow1 = bias + ((size_t)h * SEQ + qg1) * SEQ;
    const float* brow2 = bias + ((size_t)h * SEQ + qg2) * SEQ;
    const int*   mrow1 = mask + (size_t)qg1 * SEQ;
    const int*   mrow2 = mask + (size_t)qg2 * SEQ;
    __half*      prow1 = g_p16 + (bhbase + qg1) * SEQ;
    __half*      prow2 = g_p16 + (bhbase + qg2) * SEQ;

    const int rA = (wid << 4) + (lane & 7) + ((lane >> 3) & 1) * 8;

    for (int kt = 0; kt < SEQ / 64; kt++) {
        const int k0 = kt << 6;
        if (kt) __syncthreads();
        if (kt < SEQ / 64 - 1) issue_kv(kt + 1, (kt + 1) & 1);
        CP_COMMIT();
        CP_WAIT1();
        __syncthreads();

        const uint32_t base = sb + SM_TILES + (uint32_t)(kt & 1) * 16384;

        // ---- S = Q K^T over 64 cols (8 n8-groups), single fp16 term ----
        float s[8][4];
        #pragma unroll
        for (int g = 0; g < 8; g++)
            #pragma unroll
            for (int j = 0; j < 4; j++) s[g][j] = 0.0f;

        #pragma unroll
        for (int ks = 0; ks < 4; ks++) {
            uint32_t qf[4];
            const int chA = ks * 2 + (lane >> 4);
            ldsm_x4(qf, swz_addr(sb + SM_Q, rA, chA));
            #pragma unroll
            for (int nf = 0; nf < 4; nf++) {
                const int rB = nf * 16 + (lane & 7) + (lane >> 4) * 8;
                const int ch = ks * 2 + ((lane >> 3) & 1);
                uint32_t k4[4];
                ldsm_x4(k4, swz_addr(base, rB, ch));
                mma_f16(s[2*nf],   qf, k4[0], k4[1]);
                mma_f16(s[2*nf+1], qf, k4[2], k4[3]);
            }
        }

        // ---- epilogue: bias + mask + exp; fp16 P scratch store; pack frags --
        uint32_t ph[4][4];
        #pragma unroll
        for (int g = 0; g < 8; g++) {
            const int c = k0 + g * 8 + (lane & 3) * 2;
            float2 bA = *(const float2*)(brow1 + c);
            float2 bB = *(const float2*)(brow2 + c);
            int2   mA = *(const int2*)(mrow1 + c);
            int2   mB = *(const int2*)(mrow2 + c);
            float p0 = mA.x ? __expf(fmaf(s[g][0], scale, bA.x)) : 0.0f;
            float p1 = mA.y ? __expf(fmaf(s[g][1], scale, bA.y)) : 0.0f;
            float p2 = mB.x ? __expf(fmaf(s[g][2], scale, bB.x)) : 0.0f;
            float p3 = mB.y ? __expf(fmaf(s[g][3], scale, bB.y)) : 0.0f;
            rsum1 += p0 + p1;
            rsum2 += p2 + p3;
            *(uint32_t*)(prow1 + c) = h2bits(__floats2half2_rn(p0, p1));
            *(uint32_t*)(prow2 + c) = h2bits(__floats2half2_rn(p2, p3));
            const int ks = g >> 1, ix = (g & 1) * 2;
            ph[ks][ix + 0] = h2bits(__floats2half2_rn(p0 * PS, p1 * PS));
            ph[ks][ix + 1] = h2bits(__floats2half2_rn(p2 * PS, p3 * PS));
        }

        // ---- O += P V (single fp16 term): B = V via ldmatrix.trans ----
        #pragma unroll
        for (int ks = 0; ks < 4; ks++) {
            const int rV = ks * 16 + (lane & 7) + ((lane >> 3) & 1) * 8;
            #pragma unroll
            for (int dg = 0; dg < 4; dg++) {
                const int ch = 2 * dg + (lane >> 4);
                uint32_t v4[4];
                ldsm_x4t(v4, swz_addr(base + 8192, rV, ch));
                mma_f16(o[2*dg],   ph[ks], v4[0], v4[1]);
                mma_f16(o[2*dg+1], ph[ks], v4[2], v4[3]);
            }
        }
    }

    // ---- rowsum quad-reduce ----
    rsum1 += __shfl_xor_sync(0xffffffffu, rsum1, 1);
    rsum1 += __shfl_xor_sync(0xffffffffu, rsum1, 2);
    rsum2 += __shfl_xor_sync(0xffffffffu, rsum2, 1);
    rsum2 += __shfl_xor_sync(0xffffffffu, rsum2, 2);
    const float inv1 = 1.0f / rsum1;
    const float inv2 = 1.0f / rsum2;

    // normalized O (undo PS)
    const float inv1o = inv1 * (1.0f / PS);
    const float inv2o = inv2 * (1.0f / PS);
    float* or1 = outp + (bhbase + qg1) * HD;
    float* or2 = outp + (bhbase + qg2) * HD;
    #pragma unroll
    for (int g = 0; g < 8; g++) {
        const int c = g * 8 + (lane & 3) * 2;
        *(float2*)(or1 + c) = make_float2(o[g][0] * inv1o, o[g][1] * inv1o);
        *(float2*)(or2 + c) = make_float2(o[g][2] * inv2o, o[g][3] * inv2o);
    }

    // ---- fused rescale: read fp16 P scratch, write fp32 normalized attn ----
    float* rs = (float*)smem;          // 128 floats; KV smem no longer needed
    __syncthreads();                   // P stores visible block-wide; smem free
    if ((lane & 3) == 0) {
        rs[r1] = inv1;
        rs[qg2 - q0] = inv2;
    }
    __syncthreads();
    #pragma unroll 1
    for (int rr = 0; rr < 16; rr++) {
        const int qr = (wid << 4) + rr;
        const float inv = rs[qr];
        const uint4* src = (const uint4*)(g_p16 + (bhbase + q0 + qr) * SEQ);
        float4* dst = (float4*)(attn + (bhbase + q0 + qr) * SEQ);
        #pragma unroll 2
        for (int c = lane; c < SEQ / 8; c += 32) {   // 8 halfs per uint4
            uint4 hv = src[c];
            const __half2* hp = (const __half2*)&hv;
            float2 f0 = __half22float2(hp[0]);
            float2 f1 = __half22float2(hp[1]);
            float2 f2 = __half22float2(hp[2]);
            float2 f3 = __half22float2(hp[3]);
            dst[c*2+0] = make_float4(f0.x*inv, f0.y*inv, f1.x*inv, f1.y*inv);
            dst[c*2+1] = make_float4(f2.x*inv, f2.y*inv, f3.x*inv, f3.y*inv);
        }
    }
}

// ---------------------------------------------------------------------------
extern "C" void kernel_launch(void* const* d_in, const int* in_sizes, int n_in,
                              void* d_out, int out_size)
{
    const float* x    = (const float*)d_in[0];
    const float* bias = (const float*)d_in[1];
    const int*   mask = (const int*)d_in[2];
    const float* wq   = (const float*)d_in[3];
    const float* bq   = (const float*)d_in[4];
    const float* wk   = (const float*)d_in[5];
    const float* bk   = (const float*)d_in[6];
    const float* wv   = (const float*)d_in[7];
    const float* bv   = (const float*)d_in[8];

    float* outp = (float*)d_out;                       // [2,16,2048,64]
    float* attn = outp + (size_t)BH * SEQ * HD;        // [2,16,2048,2048]

    cudaFuncSetAttribute(qkv_hmma_kernel,
                         cudaFuncAttributeMaxDynamicSharedMemorySize,
                         QKV_SMEM_BYTES);
    cudaFuncSetAttribute(attn_mma_kernel,
                         cudaFuncAttributeMaxDynamicSharedMemorySize,
                         ATTN_SMEM_BYTES);

    // 0) split x to fp16 hi/lo; W to single fp16
    split_src_kernel<<<dim3(2048, 4), 256>>>(x, wq, wk, wv);

    // 1) QKV projections (fp16 2-term HMMA) -> fp16 Q/K/V
    qkv_hmma_kernel<<<dim3(DM / 128, (BSZ * SEQ) / 128, 3), 256,
                      QKV_SMEM_BYTES>>>(bq, bk, bv);

    // 2) fp16 HMMA fused attention + fused rescale (fp16 scratch)
    attn_mma_kernel<<<dim3(SEQ / 128, BH), 256, ATTN_SMEM_BYTES>>>(
        bias, mask, outp, attn);
}

// round 12
// speedup vs baseline: 1.3824x; 1.0437x over previous
#include <cuda_runtime.h>
#include <cuda_fp16.h>
#include <cstdint>

#define BSZ 2
#define NH 16
#define SEQ 2048
#define DM 1024
#define HD 64
#define BH (BSZ*NH)

// Scratch (device globals — no allocations allowed)
__device__ __half g_x16[BSZ*SEQ*DM];    // x (fp16)
__device__ __half g_w16[3*DM*DM];       // W (fp16)
__device__ __half g_q16[BH * SEQ * HD]; // q pre-scaled by 0.125*log2(e)
__device__ __half g_k16[BH * SEQ * HD];
__device__ __half g_v16[BH * SEQ * HD];
__device__ __half g_p16[(size_t)BH * SEQ * SEQ];   // unnormalized P scratch (fp16)

#define LOG2E 1.44269504f
#define QSCALE (0.125f * LOG2E)

// ---- helpers -----------------------------------------------------------------
__device__ __forceinline__ uint32_t h2bits(__half2 v) {
    return *reinterpret_cast<uint32_t*>(&v);
}
__device__ __forceinline__ float ex2(float x) {
    float y; asm("ex2.approx.ftz.f32 %0, %1;" : "=f"(y) : "f"(x)); return y;
}
__device__ __forceinline__ uint32_t smem_u32(const void* p) {
    uint32_t a;
    asm("{ .reg .u64 t; cvta.to.shared.u64 t, %1; cvt.u32.u64 %0, t; }"
        : "=r"(a) : "l"(p));
    return a;
}
// 128B-row tiles: XOR 16B-chunk by (row&7)
__device__ __forceinline__ uint32_t swz_addr(uint32_t base, int row, int chunk) {
    uint32_t off = (uint32_t)(row * 128 + chunk * 16);
    return base + (off ^ ((off >> 3) & 0x70));
}
// 64B-row tiles: SW64 swizzle
__device__ __forceinline__ uint32_t swz64_addr(uint32_t base, int row, int chunk) {
    uint32_t off = (uint32_t)(row * 64 + chunk * 16);
    return base + (off ^ ((off >> 3) & 0x30));
}
__device__ __forceinline__ void ldsm_x4(uint32_t* r, uint32_t a) {
    asm volatile("ldmatrix.sync.aligned.m8n8.x4.shared.b16 {%0,%1,%2,%3}, [%4];"
        : "=r"(r[0]), "=r"(r[1]), "=r"(r[2]), "=r"(r[3]) : "r"(a));
}
__device__ __forceinline__ void ldsm_x4t(uint32_t* r, uint32_t a) {
    asm volatile("ldmatrix.sync.aligned.m8n8.x4.trans.shared.b16 {%0,%1,%2,%3}, [%4];"
        : "=r"(r[0]), "=r"(r[1]), "=r"(r[2]), "=r"(r[3]) : "r"(a));
}
__device__ __forceinline__ void mma_f16(float* d, const uint32_t* a,
                                        uint32_t b0, uint32_t b1) {
    asm volatile("mma.sync.aligned.m16n8k16.row.col.f32.f16.f16.f32 "
        "{%0,%1,%2,%3}, {%4,%5,%6,%7}, {%8,%9}, {%0,%1,%2,%3};"
        : "+f"(d[0]), "+f"(d[1]), "+f"(d[2]), "+f"(d[3])
        : "r"(a[0]), "r"(a[1]), "r"(a[2]), "r"(a[3]), "r"(b0), "r"(b1));
}
__device__ __forceinline__ void cp16(uint32_t dst, const void* src) {
    asm volatile("cp.async.cg.shared.global [%0], [%1], 16;"
                 :: "r"(dst), "l"(src) : "memory");
}
#define CP_COMMIT() asm volatile("cp.async.commit_group;" ::: "memory")
#define CP_WAIT1()  asm volatile("cp.async.wait_group 1;" ::: "memory")

// ---------------------------------------------------------------------------
// Kernel 0: round x and W to fp16.
// ---------------------------------------------------------------------------
__global__ __launch_bounds__(256) void split_src_kernel(
    const float* __restrict__ x,
    const float* __restrict__ wq, const float* __restrict__ wk,
    const float* __restrict__ wv)
{
    const int z = blockIdx.y;
    const float* src = (z == 0) ? x : (z == 1) ? wq : (z == 2) ? wk : wv;
    uint32_t* dst = (z == 0) ? (uint32_t*)g_x16
                             : (uint32_t*)(g_w16 + (size_t)(z - 1) * DM * DM);
    const size_t n2 = (z == 0) ? (size_t)BSZ * SEQ * DM / 2
                               : (size_t)DM * DM / 2;
    for (size_t i = (size_t)blockIdx.x * 256 + threadIdx.x; i < n2;
         i += (size_t)gridDim.x * 256) {
        float2 v = ((const float2*)src)[i];
        dst[i] = h2bits(__floats2half2_rn(v.x, v.y));
    }
}

// ---------------------------------------------------------------------------
// Kernel 1: QKV projection via single-term fp16 HMMA.
// 128x128 tile, K-slab 32, 64B-row smem (SW64), double-buffered, 2 CTAs/SM.
// Q output pre-scaled by 0.125*log2e.
// ---------------------------------------------------------------------------
#define QKV_SMEM_BYTES 32768     // 2 stages x (x 8K | w 8K)

__global__ __launch_bounds__(256, 2) void qkv_hmma_kernel(
    const float* __restrict__ bq, const float* __restrict__ bk,
    const float* __restrict__ bv)
{
    extern __shared__ char smem[];
    const uint32_t sb = smem_u32(smem);
    const int tid = threadIdx.x, wid = tid >> 5, lane = tid & 31;
    const int z = blockIdx.z;
    const float* bvec = (z == 0) ? bq : (z == 1) ? bk : bv;
    __half* outp = (z == 0) ? g_q16 : (z == 1) ? g_k16 : g_v16;
    const __half* W = g_w16 + (size_t)z * DM * DM;
    const float oscale = (z == 0) ? QSCALE : 1.0f;
    const int col0 = blockIdx.x << 7;
    const int row0 = blockIdx.y << 7;

    auto issue = [&](int slab, int buf) {
        const int k0 = slab << 5;
        const uint32_t base = sb + (uint32_t)buf * 16384;
        #pragma unroll
        for (int it = 0; it < 2; it++) {
            const int idx = tid + it * 256;     // 0..511
            const int r = idx >> 2, c = idx & 3;
            uint32_t off = (uint32_t)(r * 64 + c * 16);
            off ^= (off >> 3) & 0x30;
            const size_t gx = (size_t)(row0 + r) * DM + k0 + c * 8;
            const size_t gw = (size_t)(col0 + r) * DM + k0 + c * 8;
            cp16(base + off,        g_x16 + gx);
            cp16(base + 8192 + off, W + gw);
        }
    };

    float s[16][4];
    #pragma unroll
    for (int g = 0; g < 16; g++)
        #pragma unroll
        for (int j = 0; j < 4; j++) s[g][j] = 0.0f;

    issue(0, 0);
    CP_COMMIT();

    for (int kt = 0; kt < 32; kt++) {
        if (kt) __syncthreads();
        if (kt < 31) issue(kt + 1, (kt + 1) & 1);
        CP_COMMIT();
        CP_WAIT1();
        __syncthreads();

        const uint32_t base = sb + (uint32_t)(kt & 1) * 16384;
        const int rA = (wid << 4) + (lane & 7) + ((lane >> 3) & 1) * 8;
        uint32_t ah[2][4];
        #pragma unroll
        for (int ks = 0; ks < 2; ks++) {
            const int ch = ks * 2 + (lane >> 4);
            ldsm_x4(ah[ks], swz64_addr(base, rA, ch));
        }
        #pragma unroll
        for (int nf = 0; nf < 8; nf++) {
            const int rB = nf * 16 + (lane & 7) + (lane >> 4) * 8;
            #pragma unroll
            for (int ks = 0; ks < 2; ks++) {
                const int ch = ks * 2 + ((lane >> 3) & 1);
                uint32_t w4[4];
                ldsm_x4(w4, swz64_addr(base + 8192, rB, ch));
                mma_f16(s[2*nf],   ah[ks], w4[0], w4[1]);
                mma_f16(s[2*nf+1], ah[ks], w4[2], w4[3]);
            }
        }
    }

    // epilogue: + bias (then optional q pre-scale); store fp16, head-split
    const int r1 = row0 + (wid << 4) + (lane >> 2);
    const int r2 = r1 + 8;
    const int bb1 = r1 >> 11, ss1 = r1 & (SEQ - 1);
    const int bb2 = r2 >> 11, ss2 = r2 & (SEQ - 1);
    #pragma unroll
    for (int g = 0; g < 16; g++) {
        const int c = col0 + g * 8 + (lane & 3) * 2;
        const int h = c >> 6, d = c & 63;
        float2 b2 = *(const float2*)(bvec + c);
        const size_t e1 = (((size_t)bb1 * NH + h) * SEQ + ss1) * HD + d;
        const size_t e2 = (((size_t)bb2 * NH + h) * SEQ + ss2) * HD + d;
        *(uint32_t*)&outp[e1] = h2bits(__floats2half2_rn(
            (s[g][0] + b2.x) * oscale, (s[g][1] + b2.y) * oscale));
        *(uint32_t*)&outp[e2] = h2bits(__floats2half2_rn(
            (s[g][2] + b2.x) * oscale, (s[g][3] + b2.y) * oscale));
    }
}

// ---------------------------------------------------------------------------
// Kernel 2: fp16 HMMA attention. q pre-scaled so p = ex2(s + bias*log2e).
// Unnormalized P -> fp16 scratch (same bits reused as PV fragments);
// fused rescale reads scratch, writes fp32 attn.
// blockIdx.y = h*2 + b so batch-pair CTAs share bias rows in L2.
// ---------------------------------------------------------------------------
#define SM_Q 0
#define SM_TILES 16384                 // + buf*16384: K @0, V @8192
#define ATTN_SMEM_BYTES (16384 + 2*16384)

__global__ __launch_bounds__(256, 2) void attn_mma_kernel(
    const float* __restrict__ bias,
    const int*   __restrict__ mask,
    float* __restrict__ outp,
    float* __restrict__ attn)
{
    extern __shared__ char smem[];
    const uint32_t sb = smem_u32(smem);

    const int tid = threadIdx.x;
    const int wid = tid >> 5, lane = tid & 31;
    const int h  = blockIdx.y >> 1;            // bias row set
    const int b  = blockIdx.y & 1;             // batch
    const int bh = b * NH + h;
    const int q0 = blockIdx.x << 7;
    const size_t bhbase = (size_t)bh * SEQ;

    auto issue_kv = [&](int kt, int buf) {
        const int k0 = kt << 6;
        const uint32_t base = sb + SM_TILES + (uint32_t)buf * 16384;
        const char* kk = (const char*)(g_k16 + (bhbase + k0) * HD);
        const char* vv = (const char*)(g_v16 + (bhbase + k0) * HD);
        #pragma unroll
        for (int it = 0; it < 2; it++) {
            const int idx = tid + it * 256;     // 0..511
            const uint32_t off = (uint32_t)(idx << 4);
            const uint32_t dst = off ^ ((off >> 3) & 0x70);
            cp16(base + dst,        kk + off);
            cp16(base + 8192 + dst, vv + off);
        }
    };

    // prologue: Q tile (128x64 fp16 = 16KB) + K/V(0)
    {
        const char* qq = (const char*)(g_q16 + (bhbase + q0) * HD);
        #pragma unroll
        for (int it = 0; it < 4; it++) {
            const int idx = tid + it * 256;     // 0..1023
            const uint32_t off = (uint32_t)(idx << 4);
            const uint32_t dst = off ^ ((off >> 3) & 0x70);
            cp16(sb + SM_Q + dst, qq + off);
        }
    }
    issue_kv(0, 0);
    CP_COMMIT();

    float o[8][4];
    #pragma unroll
    for (int g = 0; g < 8; g++)
        #pragma unroll
        for (int j = 0; j < 4; j++) o[g][j] = 0.0f;
    float rsum1 = 0.0f, rsum2 = 0.0f;

    const int r1 = (wid << 4) + (lane >> 2);
    const int qg1 = q0 + r1, qg2 = qg1 + 8;
    const float* brow1 = bias + ((size_t)h * SEQ + qg1) * SEQ;
    const float* brow2 = bias + ((size_t)h * SEQ + qg2) * SEQ;
    const int*   mrow1 = mask + (size_t)qg1 * SEQ;
    const int*   mrow2 = mask + (size_t)qg2 * SEQ;
    __half*      prow1 = g_p16 + (bhbase + qg1) * SEQ;
    __half*      prow2 = g_p16 + (bhbase + qg2) * SEQ;

    const int rA = (wid << 4) + (lane & 7) + ((lane >> 3) & 1) * 8;

    for (int kt = 0; kt < SEQ / 64; kt++) {
        const int k0 = kt << 6;
        if (kt) __syncthreads();
        if (kt < SEQ / 64 - 1) issue_kv(kt + 1, (kt + 1) & 1);
        CP_COMMIT();
        CP_WAIT1();
        __syncthreads();

        const uint32_t base = sb + SM_TILES + (uint32_t)(kt & 1) * 16384;

        // ---- S' = Q' K^T over 64 cols (already scaled by 0.125*log2e) ----
        float s[8][4];
        #pragma unroll
        for (int g = 0; g < 8; g++)
            #pragma unroll
            for (int j = 0; j < 4; j++) s[g][j] = 0.0f;

        #pragma unroll
        for (int ks = 0; ks < 4; ks++) {
            uint32_t qf[4];
            const int chA = ks * 2 + (lane >> 4);
            ldsm_x4(qf, swz_addr(sb + SM_Q, rA, chA));
            #pragma unroll
            for (int nf = 0; nf < 4; nf++) {
                const int rB = nf * 16 + (lane & 7) + (lane >> 4) * 8;
                const int ch = ks * 2 + ((lane >> 3) & 1);
                uint32_t k4[4];
                ldsm_x4(k4, swz_addr(base, rB, ch));
                mma_f16(s[2*nf],   qf, k4[0], k4[1]);
                mma_f16(s[2*nf+1], qf, k4[2], k4[3]);
            }
        }

        // ---- epilogue: p = ex2(s + bias*log2e); fp16 P (scratch + frags) ----
        uint32_t ph[4][4];
        #pragma unroll
        for (int g = 0; g < 8; g++) {
            const int c = k0 + g * 8 + (lane & 3) * 2;
            float2 bA = *(const float2*)(brow1 + c);
            float2 bB = *(const float2*)(brow2 + c);
            int2   mA = *(const int2*)(mrow1 + c);
            int2   mB = *(const int2*)(mrow2 + c);
            float p0 = mA.x ? ex2(fmaf(bA.x, LOG2E, s[g][0])) : 0.0f;
            float p1 = mA.y ? ex2(fmaf(bA.y, LOG2E, s[g][1])) : 0.0f;
            float p2 = mB.x ? ex2(fmaf(bB.x, LOG2E, s[g][2])) : 0.0f;
            float p3 = mB.y ? ex2(fmaf(bB.y, LOG2E, s[g][3])) : 0.0f;
            rsum1 += p0 + p1;
            rsum2 += p2 + p3;
            const uint32_t h01 = h2bits(__floats2half2_rn(p0, p1));
            const uint32_t h23 = h2bits(__floats2half2_rn(p2, p3));
            *(uint32_t*)(prow1 + c) = h01;
            *(uint32_t*)(prow2 + c) = h23;
            const int ks = g >> 1, ix = (g & 1) * 2;
            ph[ks][ix + 0] = h01;
            ph[ks][ix + 1] = h23;
        }

        // ---- O += P V (single fp16 term): B = V via ldmatrix.trans ----
        #pragma unroll
        for (int ks = 0; ks < 4; ks++) {
            const int rV = ks * 16 + (lane & 7) + ((lane >> 3) & 1) * 8;
            #pragma unroll
            for (int dg = 0; dg < 4; dg++) {
                const int ch = 2 * dg + (lane >> 4);
                uint32_t v4[4];
                ldsm_x4t(v4, swz_addr(base + 8192, rV, ch));
                mma_f16(o[2*dg],   ph[ks], v4[0], v4[1]);
                mma_f16(o[2*dg+1], ph[ks], v4[2], v4[3]);
            }
        }
    }

    // ---- rowsum quad-reduce ----
    rsum1 += __shfl_xor_sync(0xffffffffu, rsum1, 1);
    rsum1 += __shfl_xor_sync(0xffffffffu, rsum1, 2);
    rsum2 += __shfl_xor_sync(0xffffffffu, rsum2, 1);
    rsum2 += __shfl_xor_sync(0xffffffffu, rsum2, 2);
    const float inv1 = 1.0f / rsum1;
    const float inv2 = 1.0f / rsum2;

    // normalized O
    float* or1 = outp + (bhbase + qg1) * HD;
    float* or2 = outp + (bhbase + qg2) * HD;
    #pragma unroll
    for (int g = 0; g < 8; g++) {
        const int c = g * 8 + (lane & 3) * 2;
        *(float2*)(or1 + c) = make_float2(o[g][0] * inv1, o[g][1] * inv1);
        *(float2*)(or2 + c) = make_float2(o[g][2] * inv2, o[g][3] * inv2);
    }

    // ---- fused rescale: read fp16 P scratch, write fp32 normalized attn ----
    float* rs = (float*)smem;          // 128 floats; KV smem no longer needed
    __syncthreads();                   // P stores visible block-wide; smem free
    if ((lane & 3) == 0) {
        rs[r1] = inv1;
        rs[qg2 - q0] = inv2;
    }
    __syncthreads();
    #pragma unroll 1
    for (int rr = 0; rr < 16; rr++) {
        const int qr = (wid << 4) + rr;
        const float inv = rs[qr];
        const uint4* src = (const uint4*)(g_p16 + (bhbase + q0 + qr) * SEQ);
        float4* dst = (float4*)(attn + (bhbase + q0 + qr) * SEQ);
        #pragma unroll 2
        for (int c = lane; c < SEQ / 8; c += 32) {   // 8 halfs per uint4
            uint4 hv = src[c];
            const __half2* hp = (const __half2*)&hv;
            float2 f0 = __half22float2(hp[0]);
            float2 f1 = __half22float2(hp[1]);
            float2 f2 = __half22float2(hp[2]);
            float2 f3 = __half22float2(hp[3]);
            dst[c*2+0] = make_float4(f0.x*inv, f0.y*inv, f1.x*inv, f1.y*inv);
            dst[c*2+1] = make_float4(f2.x*inv, f2.y*inv, f3.x*inv, f3.y*inv);
        }
    }
}

// ---------------------------------------------------------------------------
extern "C" void kernel_launch(void* const* d_in, const int* in_sizes, int n_in,
                              void* d_out, int out_size)
{
    const float* x    = (const float*)d_in[0];
    const float* bias = (const float*)d_in[1];
    const int*   mask = (const int*)d_in[2];
    const float* wq   = (const float*)d_in[3];
    const float* bq   = (const float*)d_in[4];
    const float* wk   = (const float*)d_in[5];
    const float* bk   = (const float*)d_in[6];
    const float* wv   = (const float*)d_in[7];
    const float* bv   = (const float*)d_in[8];

    float* outp = (float*)d_out;                       // [2,16,2048,64]
    float* attn = outp + (size_t)BH * SEQ * HD;        // [2,16,2048,2048]

    cudaFuncSetAttribute(qkv_hmma_kernel,
                         cudaFuncAttributeMaxDynamicSharedMemorySize,
                         QKV_SMEM_BYTES);
    cudaFuncSetAttribute(attn_mma_kernel,
                         cudaFuncAttributeMaxDynamicSharedMemorySize,
                         ATTN_SMEM_BYTES);

    // 0) round x / W to fp16
    split_src_kernel<<<dim3(2048, 4), 256>>>(x, wq, wk, wv);

    // 1) QKV projections (single-term fp16 HMMA); q pre-scaled
    qkv_hmma_kernel<<<dim3(DM / 128, (BSZ * SEQ) / 128, 3), 256,
                      QKV_SMEM_BYTES>>>(bq, bk, bv);

    // 2) fp16 HMMA fused attention + fused rescale
    attn_mma_kernel<<<dim3(SEQ / 128, BH), 256, ATTN_SMEM_BYTES>>>(
        bias, mask, outp, attn);
}

// round 13
// speedup vs baseline: 1.4198x; 1.0270x over previous
#include <cuda_runtime.h>
#include <cuda_fp16.h>
#include <cstdint>

#define BSZ 2
#define NH 16
#define SEQ 2048
#define DM 1024
#define HD 64
#define BH (BSZ*NH)

// Scratch (device globals — no allocations allowed)
__device__ __half g_x16[BSZ*SEQ*DM];    // x (fp16)
__device__ __half g_w16[3*DM*DM];       // W (fp16)
__device__ __half g_q16[BH * SEQ * HD]; // q pre-scaled by 0.125*log2(e)
__device__ __half g_k16[BH * SEQ * HD];
__device__ __half g_v16[BH * SEQ * HD];
__device__ __half g_p16[(size_t)BH * SEQ * SEQ];   // unnormalized P scratch (fp16)
__device__ float  g_bm[(size_t)NH * SEQ * SEQ];    // premasked bias * log2e (fp32)

#define LOG2E 1.44269504f
#define QSCALE (0.125f * LOG2E)
#define ONES2  0x3C003C00u      // half2(1.0, 1.0)

// ---- helpers -----------------------------------------------------------------
__device__ __forceinline__ uint32_t h2bits(__half2 v) {
    return *reinterpret_cast<uint32_t*>(&v);
}
__device__ __forceinline__ float ex2(float x) {
    float y; asm("ex2.approx.ftz.f32 %0, %1;" : "=f"(y) : "f"(x)); return y;
}
__device__ __forceinline__ uint32_t smem_u32(const void* p) {
    uint32_t a;
    asm("{ .reg .u64 t; cvta.to.shared.u64 t, %1; cvt.u32.u64 %0, t; }"
        : "=r"(a) : "l"(p));
    return a;
}
// 128B-row tiles: XOR 16B-chunk by (row&7)
__device__ __forceinline__ uint32_t swz_addr(uint32_t base, int row, int chunk) {
    uint32_t off = (uint32_t)(row * 128 + chunk * 16);
    return base + (off ^ ((off >> 3) & 0x70));
}
// 64B-row tiles: SW64 swizzle
__device__ __forceinline__ uint32_t swz64_addr(uint32_t base, int row, int chunk) {
    uint32_t off = (uint32_t)(row * 64 + chunk * 16);
    return base + (off ^ ((off >> 3) & 0x30));
}
__device__ __forceinline__ void ldsm_x4(uint32_t* r, uint32_t a) {
    asm volatile("ldmatrix.sync.aligned.m8n8.x4.shared.b16 {%0,%1,%2,%3}, [%4];"
        : "=r"(r[0]), "=r"(r[1]), "=r"(r[2]), "=r"(r[3]) : "r"(a));
}
__device__ __forceinline__ void ldsm_x4t(uint32_t* r, uint32_t a) {
    asm volatile("ldmatrix.sync.aligned.m8n8.x4.trans.shared.b16 {%0,%1,%2,%3}, [%4];"
        : "=r"(r[0]), "=r"(r[1]), "=r"(r[2]), "=r"(r[3]) : "r"(a));
}
__device__ __forceinline__ void mma_f16(float* d, const uint32_t* a,
                                        uint32_t b0, uint32_t b1) {
    asm volatile("mma.sync.aligned.m16n8k16.row.col.f32.f16.f16.f32 "
        "{%0,%1,%2,%3}, {%4,%5,%6,%7}, {%8,%9}, {%0,%1,%2,%3};"
        : "+f"(d[0]), "+f"(d[1]), "+f"(d[2]), "+f"(d[3])
        : "r"(a[0]), "r"(a[1]), "r"(a[2]), "r"(a[3]), "r"(b0), "r"(b1));
}
__device__ __forceinline__ void cp16(uint32_t dst, const void* src) {
    asm volatile("cp.async.cg.shared.global [%0], [%1], 16;"
                 :: "r"(dst), "l"(src) : "memory");
}
#define CP_COMMIT() asm volatile("cp.async.commit_group;" ::: "memory")
#define CP_WAIT1()  asm volatile("cp.async.wait_group 1;" ::: "memory")

// ---------------------------------------------------------------------------
// Kernel 0a: round x and W to fp16.
// ---------------------------------------------------------------------------
__global__ __launch_bounds__(256) void split_src_kernel(
    const float* __restrict__ x,
    const float* __restrict__ wq, const float* __restrict__ wk,
    const float* __restrict__ wv)
{
    const int z = blockIdx.y;
    const float* src = (z == 0) ? x : (z == 1) ? wq : (z == 2) ? wk : wv;
    uint32_t* dst = (z == 0) ? (uint32_t*)g_x16
                             : (uint32_t*)(g_w16 + (size_t)(z - 1) * DM * DM);
    const size_t n2 = (z == 0) ? (size_t)BSZ * SEQ * DM / 2
                               : (size_t)DM * DM / 2;
    for (size_t i = (size_t)blockIdx.x * 256 + threadIdx.x; i < n2;
         i += (size_t)gridDim.x * 256) {
        float2 v = ((const float2*)src)[i];
        dst[i] = h2bits(__floats2half2_rn(v.x, v.y));
    }
}

// ---------------------------------------------------------------------------
// Kernel 0b: premask + prescale bias: bm = mask ? bias*log2e : -1e9.
// Mask read once per (q,k); all 16 heads processed per thread.
// ---------------------------------------------------------------------------
__global__ __launch_bounds__(256) void prep_bias_kernel(
    const float* __restrict__ bias, const int* __restrict__ mask)
{
    const size_t i = (size_t)blockIdx.x * 256 + threadIdx.x;  // over SEQ*SEQ/2
    int2 m = ((const int2*)mask)[i];
    #pragma unroll 4
    for (int h = 0; h < NH; h++) {
        float2 bv = ((const float2*)(bias + (size_t)h * SEQ * SEQ))[i];
        float2 o;
        o.x = m.x ? bv.x * LOG2E : -1e9f;
        o.y = m.y ? bv.y * LOG2E : -1e9f;
        ((float2*)(g_bm + (size_t)h * SEQ * SEQ))[i] = o;
    }
}

// ---------------------------------------------------------------------------
// Kernel 1: QKV projection via single-term fp16 HMMA.
// 128x128 tile, K-slab 32, 64B-row smem (SW64), double-buffered, 2 CTAs/SM.
// Q output pre-scaled by 0.125*log2e.
// ---------------------------------------------------------------------------
#define QKV_SMEM_BYTES 32768     // 2 stages x (x 8K | w 8K)

__global__ __launch_bounds__(256, 2) void qkv_hmma_kernel(
    const float* __restrict__ bq, const float* __restrict__ bk,
    const float* __restrict__ bv)
{
    extern __shared__ char smem[];
    const uint32_t sb = smem_u32(smem);
    const int tid = threadIdx.x, wid = tid >> 5, lane = tid & 31;
    const int z = blockIdx.z;
    const float* bvec = (z == 0) ? bq : (z == 1) ? bk : bv;
    __half* outp = (z == 0) ? g_q16 : (z == 1) ? g_k16 : g_v16;
    const __half* W = g_w16 + (size_t)z * DM * DM;
    const float oscale = (z == 0) ? QSCALE : 1.0f;
    const int col0 = blockIdx.x << 7;
    const int row0 = blockIdx.y << 7;

    auto issue = [&](int slab, int buf) {
        const int k0 = slab << 5;
        const uint32_t base = sb + (uint32_t)buf * 16384;
        #pragma unroll
        for (int it = 0; it < 2; it++) {
            const int idx = tid + it * 256;     // 0..511
            const int r = idx >> 2, c = idx & 3;
            uint32_t off = (uint32_t)(r * 64 + c * 16);
            off ^= (off >> 3) & 0x30;
            const size_t gx = (size_t)(row0 + r) * DM + k0 + c * 8;
            const size_t gw = (size_t)(col0 + r) * DM + k0 + c * 8;
            cp16(base + off,        g_x16 + gx);
            cp16(base + 8192 + off, W + gw);
        }
    };

    float s[16][4];
    #pragma unroll
    for (int g = 0; g < 16; g++)
        #pragma unroll
        for (int j = 0; j < 4; j++) s[g][j] = 0.0f;

    issue(0, 0);
    CP_COMMIT();

    for (int kt = 0; kt < 32; kt++) {
        if (kt) __syncthreads();
        if (kt < 31) issue(kt + 1, (kt + 1) & 1);
        CP_COMMIT();
        CP_WAIT1();
        __syncthreads();

        const uint32_t base = sb + (uint32_t)(kt & 1) * 16384;
        const int rA = (wid << 4) + (lane & 7) + ((lane >> 3) & 1) * 8;
        uint32_t ah[2][4];
        #pragma unroll
        for (int ks = 0; ks < 2; ks++) {
            const int ch = ks * 2 + (lane >> 4);
            ldsm_x4(ah[ks], swz64_addr(base, rA, ch));
        }
        #pragma unroll
        for (int nf = 0; nf < 8; nf++) {
            const int rB = nf * 16 + (lane & 7) + (lane >> 4) * 8;
            #pragma unroll
            for (int ks = 0; ks < 2; ks++) {
                const int ch = ks * 2 + ((lane >> 3) & 1);
                uint32_t w4[4];
                ldsm_x4(w4, swz64_addr(base + 8192, rB, ch));
                mma_f16(s[2*nf],   ah[ks], w4[0], w4[1]);
                mma_f16(s[2*nf+1], ah[ks], w4[2], w4[3]);
            }
        }
    }

    // epilogue: + bias (then optional q pre-scale); store fp16, head-split
    const int r1 = row0 + (wid << 4) + (lane >> 2);
    const int r2 = r1 + 8;
    const int bb1 = r1 >> 11, ss1 = r1 & (SEQ - 1);
    const int bb2 = r2 >> 11, ss2 = r2 & (SEQ - 1);
    #pragma unroll
    for (int g = 0; g < 16; g++) {
        const int c = col0 + g * 8 + (lane & 3) * 2;
        const int h = c >> 6, d = c & 63;
        float2 b2 = *(const float2*)(bvec + c);
        const size_t e1 = (((size_t)bb1 * NH + h) * SEQ + ss1) * HD + d;
        const size_t e2 = (((size_t)bb2 * NH + h) * SEQ + ss2) * HD + d;
        *(uint32_t*)&outp[e1] = h2bits(__floats2half2_rn(
            (s[g][0] + b2.x) * oscale, (s[g][1] + b2.y) * oscale));
        *(uint32_t*)&outp[e2] = h2bits(__floats2half2_rn(
            (s[g][2] + b2.x) * oscale, (s[g][3] + b2.y) * oscale));
    }
}

// ---------------------------------------------------------------------------
// Kernel 2: fp16 HMMA attention. p = ex2(s + bm) (bm premasked+prescaled,
// ex2(-1e9)=0 handles masking). Rowsum via ones-MMA on the tensor pipe.
// Unnormalized P -> fp16 scratch; fused rescale writes fp32 attn.
// blockIdx.y = h*2 + b so batch-pair CTAs share bm rows in L2.
// ---------------------------------------------------------------------------
#define SM_Q 0
#define SM_TILES 16384                 // + buf*16384: K @0, V @8192
#define ATTN_SMEM_BYTES (16384 + 2*16384)

__global__ __launch_bounds__(256, 2) void attn_mma_kernel(
    float* __restrict__ outp,
    float* __restrict__ attn)
{
    extern __shared__ char smem[];
    const uint32_t sb = smem_u32(smem);

    const int tid = threadIdx.x;
    const int wid = tid >> 5, lane = tid & 31;
    const int h  = blockIdx.y >> 1;            // bias row set
    const int b  = blockIdx.y & 1;             // batch
    const int bh = b * NH + h;
    const int q0 = blockIdx.x << 7;
    const size_t bhbase = (size_t)bh * SEQ;

    auto issue_kv = [&](int kt, int buf) {
        const int k0 = kt << 6;
        const uint32_t base = sb + SM_TILES + (uint32_t)buf * 16384;
        const char* kk = (const char*)(g_k16 + (bhbase + k0) * HD);
        const char* vv = (const char*)(g_v16 + (bhbase + k0) * HD);
        #pragma unroll
        for (int it = 0; it < 2; it++) {
            const int idx = tid + it * 256;     // 0..511
            const uint32_t off = (uint32_t)(idx << 4);
            const uint32_t dst = off ^ ((off >> 3) & 0x70);
            cp16(base + dst,        kk + off);
            cp16(base + 8192 + dst, vv + off);
        }
    };

    // prologue: Q tile (128x64 fp16 = 16KB) + K/V(0)
    {
        const char* qq = (const char*)(g_q16 + (bhbase + q0) * HD);
        #pragma unroll
        for (int it = 0; it < 4; it++) {
            const int idx = tid + it * 256;     // 0..1023
            const uint32_t off = (uint32_t)(idx << 4);
            const uint32_t dst = off ^ ((off >> 3) & 0x70);
            cp16(sb + SM_Q + dst, qq + off);
        }
    }
    issue_kv(0, 0);
    CP_COMMIT();

    float o[8][4];
    #pragma unroll
    for (int g = 0; g < 8; g++)
        #pragma unroll
        for (int j = 0; j < 4; j++) o[g][j] = 0.0f;
    float racc[4] = {0.0f, 0.0f, 0.0f, 0.0f};   // ones-MMA rowsum accumulator

    const int r1 = (wid << 4) + (lane >> 2);
    const int qg1 = q0 + r1, qg2 = qg1 + 8;
    const float* bmrow1 = g_bm + ((size_t)h * SEQ + qg1) * SEQ;
    const float* bmrow2 = g_bm + ((size_t)h * SEQ + qg2) * SEQ;
    __half*      prow1 = g_p16 + (bhbase + qg1) * SEQ;
    __half*      prow2 = g_p16 + (bhbase + qg2) * SEQ;

    const int rA = (wid << 4) + (lane & 7) + ((lane >> 3) & 1) * 8;

    for (int kt = 0; kt < SEQ / 64; kt++) {
        const int k0 = kt << 6;
        if (kt) __syncthreads();
        if (kt < SEQ / 64 - 1) issue_kv(kt + 1, (kt + 1) & 1);
        CP_COMMIT();
        CP_WAIT1();
        __syncthreads();

        const uint32_t base = sb + SM_TILES + (uint32_t)(kt & 1) * 16384;

        // ---- S' = Q' K^T over 64 cols (already scaled by 0.125*log2e) ----
        float s[8][4];
        #pragma unroll
        for (int g = 0; g < 8; g++)
            #pragma unroll
            for (int j = 0; j < 4; j++) s[g][j] = 0.0f;

        #pragma unroll
        for (int ks = 0; ks < 4; ks++) {
            uint32_t qf[4];
            const int chA = ks * 2 + (lane >> 4);
            ldsm_x4(qf, swz_addr(sb + SM_Q, rA, chA));
            #pragma unroll
            for (int nf = 0; nf < 4; nf++) {
                const int rB = nf * 16 + (lane & 7) + (lane >> 4) * 8;
                const int ch = ks * 2 + ((lane >> 3) & 1);
                uint32_t k4[4];
                ldsm_x4(k4, swz_addr(base, rB, ch));
                mma_f16(s[2*nf],   qf, k4[0], k4[1]);
                mma_f16(s[2*nf+1], qf, k4[2], k4[3]);
            }
        }

        // ---- epilogue: p = ex2(s + bm); fp16 P (scratch + frags) ----
        uint32_t ph[4][4];
        #pragma unroll
        for (int g = 0; g < 8; g++) {
            const int c = k0 + g * 8 + (lane & 3) * 2;
            float2 bA = *(const float2*)(bmrow1 + c);
            float2 bB = *(const float2*)(bmrow2 + c);
            float p0 = ex2(s[g][0] + bA.x);
            float p1 = ex2(s[g][1] + bA.y);
            float p2 = ex2(s[g][2] + bB.x);
            float p3 = ex2(s[g][3] + bB.y);
            const uint32_t h01 = h2bits(__floats2half2_rn(p0, p1));
            const uint32_t h23 = h2bits(__floats2half2_rn(p2, p3));
            *(uint32_t*)(prow1 + c) = h01;
            *(uint32_t*)(prow2 + c) = h23;
            const int ks = g >> 1, ix = (g & 1) * 2;
            ph[ks][ix + 0] = h01;
            ph[ks][ix + 1] = h23;
        }

        // ---- O += P V; rowsum += P x ones (tensor pipe) ----
        #pragma unroll
        for (int ks = 0; ks < 4; ks++) {
            mma_f16(racc, ph[ks], ONES2, ONES2);
            const int rV = ks * 16 + (lane & 7) + ((lane >> 3) & 1) * 8;
            #pragma unroll
            for (int dg = 0; dg < 4; dg++) {
                const int ch = 2 * dg + (lane >> 4);
                uint32_t v4[4];
                ldsm_x4t(v4, swz_addr(base + 8192, rV, ch));
                mma_f16(o[2*dg],   ph[ks], v4[0], v4[1]);
                mma_f16(o[2*dg+1], ph[ks], v4[2], v4[3]);
            }
        }
    }

    // ---- rowsums come straight from the ones-MMA accumulator ----
    const float inv1 = 1.0f / racc[0];
    const float inv2 = 1.0f / racc[2];

    // normalized O
    float* or1 = outp + (bhbase + qg1) * HD;
    float* or2 = outp + (bhbase + qg2) * HD;
    #pragma unroll
    for (int g = 0; g < 8; g++) {
        const int c = g * 8 + (lane & 3) * 2;
        *(float2*)(or1 + c) = make_float2(o[g][0] * inv1, o[g][1] * inv1);
        *(float2*)(or2 + c) = make_float2(o[g][2] * inv2, o[g][3] * inv2);
    }

    // ---- fused rescale: read fp16 P scratch, write fp32 normalized attn ----
    float* rs = (float*)smem;          // 128 floats; KV smem no longer needed
    __syncthreads();                   // P stores visible block-wide; smem free
    if ((lane & 3) == 0) {
        rs[r1] = inv1;
        rs[qg2 - q0] = inv2;
    }
    __syncthreads();
    #pragma unroll 1
    for (int rr = 0; rr < 16; rr++) {
        const int qr = (wid << 4) + rr;
        const float inv = rs[qr];
        const uint4* src = (const uint4*)(g_p16 + (bhbase + q0 + qr) * SEQ);
        float4* dst = (float4*)(attn + (bhbase + q0 + qr) * SEQ);
        #pragma unroll 2
        for (int c = lane; c < SEQ / 8; c += 32) {   // 8 halfs per uint4
            uint4 hv = src[c];
            const __half2* hp = (const __half2*)&hv;
            float2 f0 = __half22float2(hp[0]);
            float2 f1 = __half22float2(hp[1]);
            float2 f2 = __half22float2(hp[2]);
            float2 f3 = __half22float2(hp[3]);
            dst[c*2+0] = make_float4(f0.x*inv, f0.y*inv, f1.x*inv, f1.y*inv);
            dst[c*2+1] = make_float4(f2.x*inv, f2.y*inv, f3.x*inv, f3.y*inv);
        }
    }
}

// ---------------------------------------------------------------------------
extern "C" void kernel_launch(void* const* d_in, const int* in_sizes, int n_in,
                              void* d_out, int out_size)
{
    const float* x    = (const float*)d_in[0];
    const float* bias = (const float*)d_in[1];
    const int*   mask = (const int*)d_in[2];
    const float* wq   = (const float*)d_in[3];
    const float* bq   = (const float*)d_in[4];
    const float* wk   = (const float*)d_in[5];
    const float* bk   = (const float*)d_in[6];
    const float* wv   = (const float*)d_in[7];
    const float* bv   = (const float*)d_in[8];

    float* outp = (float*)d_out;                       // [2,16,2048,64]
    float* attn = outp + (size_t)BH * SEQ * HD;        // [2,16,2048,2048]

    cudaFuncSetAttribute(qkv_hmma_kernel,
                         cudaFuncAttributeMaxDynamicSharedMemorySize,
                         QKV_SMEM_BYTES);
    cudaFuncSetAttribute(attn_mma_kernel,
                         cudaFuncAttributeMaxDynamicSharedMemorySize,
                         ATTN_SMEM_BYTES);

    // 0a) round x / W to fp16
    split_src_kernel<<<dim3(2048, 4), 256>>>(x, wq, wk, wv);

    // 0b) premask + prescale bias
    prep_bias_kernel<<<dim3(SEQ * SEQ / 2 / 256), 256>>>(bias, mask);

    // 1) QKV projections (single-term fp16 HMMA); q pre-scaled
    qkv_hmma_kernel<<<dim3(DM / 128, (BSZ * SEQ) / 128, 3), 256,
                      QKV_SMEM_BYTES>>>(bq, bk, bv);

    // 2) fp16 HMMA fused attention + fused rescale
    attn_mma_kernel<<<dim3(SEQ / 128, BH * 2 / 2), 256, ATTN_SMEM_BYTES>>>(
        outp, attn);
}

// round 14
// speedup vs baseline: 1.7633x; 1.2419x over previous
#include <cuda_runtime.h>
#include <cuda_fp16.h>
#include <cstdint>

#define BSZ 2
#define NH 16
#define SEQ 2048
#define DM 1024
#define HD 64
#define BH (BSZ*NH)

// Scratch (device globals — no allocations allowed)
__device__ __half g_x16[BSZ*SEQ*DM];    // x (fp16)
__device__ __half g_w16[3*DM*DM];       // W (fp16)
__device__ __half g_q16[BH * SEQ * HD]; // q pre-scaled by 0.125*log2(e)
__device__ __half g_k16[BH * SEQ * HD];
__device__ __half g_v16[BH * SEQ * HD];
__device__ __half g_p16[(size_t)BH * SEQ * SEQ];   // unnormalized P scratch (fp16)
__device__ __half g_bmh[(size_t)NH * SEQ * SEQ];   // premasked bias*log2e (fp16)

#define LOG2E 1.44269504f
#define QSCALE (0.125f * LOG2E)
#define ONES2  0x3C003C00u      // half2(1.0, 1.0)
#define MASKV  (-60000.0f)      // fp16-safe "minus infinity" (ex2 -> 0)

// ---- helpers -----------------------------------------------------------------
__device__ __forceinline__ uint32_t h2bits(__half2 v) {
    return *reinterpret_cast<uint32_t*>(&v);
}
__device__ __forceinline__ float ex2(float x) {
    float y; asm("ex2.approx.ftz.f32 %0, %1;" : "=f"(y) : "f"(x)); return y;
}
__device__ __forceinline__ uint32_t smem_u32(const void* p) {
    uint32_t a;
    asm("{ .reg .u64 t; cvta.to.shared.u64 t, %1; cvt.u32.u64 %0, t; }"
        : "=r"(a) : "l"(p));
    return a;
}
// 128B-row tiles: XOR 16B-chunk by (row&7)
__device__ __forceinline__ uint32_t swz_addr(uint32_t base, int row, int chunk) {
    uint32_t off = (uint32_t)(row * 128 + chunk * 16);
    return base + (off ^ ((off >> 3) & 0x70));
}
// 64B-row tiles: SW64 swizzle
__device__ __forceinline__ uint32_t swz64_addr(uint32_t base, int row, int chunk) {
    uint32_t off = (uint32_t)(row * 64 + chunk * 16);
    return base + (off ^ ((off >> 3) & 0x30));
}
__device__ __forceinline__ void ldsm_x4(uint32_t* r, uint32_t a) {
    asm volatile("ldmatrix.sync.aligned.m8n8.x4.shared.b16 {%0,%1,%2,%3}, [%4];"
        : "=r"(r[0]), "=r"(r[1]), "=r"(r[2]), "=r"(r[3]) : "r"(a));
}
__device__ __forceinline__ void ldsm_x4t(uint32_t* r, uint32_t a) {
    asm volatile("ldmatrix.sync.aligned.m8n8.x4.trans.shared.b16 {%0,%1,%2,%3}, [%4];"
        : "=r"(r[0]), "=r"(r[1]), "=r"(r[2]), "=r"(r[3]) : "r"(a));
}
__device__ __forceinline__ void mma_f16(float* d, const uint32_t* a,
                                        uint32_t b0, uint32_t b1) {
    asm volatile("mma.sync.aligned.m16n8k16.row.col.f32.f16.f16.f32 "
        "{%0,%1,%2,%3}, {%4,%5,%6,%7}, {%8,%9}, {%0,%1,%2,%3};"
        : "+f"(d[0]), "+f"(d[1]), "+f"(d[2]), "+f"(d[3])
        : "r"(a[0]), "r"(a[1]), "r"(a[2]), "r"(a[3]), "r"(b0), "r"(b1));
}
__device__ __forceinline__ void cp16(uint32_t dst, const void* src) {
    asm volatile("cp.async.cg.shared.global [%0], [%1], 16;"
                 :: "r"(dst), "l"(src) : "memory");
}
#define CP_COMMIT() asm volatile("cp.async.commit_group;" ::: "memory")
#define CP_WAIT1()  asm volatile("cp.async.wait_group 1;" ::: "memory")

// ---------------------------------------------------------------------------
// Kernel 0a: round x and W to fp16.
// ---------------------------------------------------------------------------
__global__ __launch_bounds__(256) void split_src_kernel(
    const float* __restrict__ x,
    const float* __restrict__ wq, const float* __restrict__ wk,
    const float* __restrict__ wv)
{
    const int z = blockIdx.y;
    const float* src = (z == 0) ? x : (z == 1) ? wq : (z == 2) ? wk : wv;
    uint32_t* dst = (z == 0) ? (uint32_t*)g_x16
                             : (uint32_t*)(g_w16 + (size_t)(z - 1) * DM * DM);
    const size_t n2 = (z == 0) ? (size_t)BSZ * SEQ * DM / 2
                               : (size_t)DM * DM / 2;
    for (size_t i = (size_t)blockIdx.x * 256 + threadIdx.x; i < n2;
         i += (size_t)gridDim.x * 256) {
        float2 v = ((const float2*)src)[i];
        dst[i] = h2bits(__floats2half2_rn(v.x, v.y));
    }
}

// ---------------------------------------------------------------------------
// Kernel 0b: premask + prescale bias to fp16: bm = mask ? bias*log2e : -60000.
// ---------------------------------------------------------------------------
__global__ __launch_bounds__(256) void prep_bias_kernel(
    const float* __restrict__ bias, const int* __restrict__ mask)
{
    const size_t i = (size_t)blockIdx.x * 256 + threadIdx.x;  // over SEQ*SEQ/2
    int2 m = ((const int2*)mask)[i];
    #pragma unroll 4
    for (int h = 0; h < NH; h++) {
        float2 bv = ((const float2*)(bias + (size_t)h * SEQ * SEQ))[i];
        float ox = m.x ? bv.x * LOG2E : MASKV;
        float oy = m.y ? bv.y * LOG2E : MASKV;
        ((uint32_t*)(g_bmh + (size_t)h * SEQ * SEQ))[i] =
            h2bits(__floats2half2_rn(ox, oy));
    }
}

// ---------------------------------------------------------------------------
// Kernel 1: QKV projection via single-term fp16 HMMA.
// 128x128 tile, K-slab 32, 64B-row smem (SW64), double-buffered, 2 CTAs/SM.
// Q output pre-scaled by 0.125*log2e.
// ---------------------------------------------------------------------------
#define QKV_SMEM_BYTES 32768     // 2 stages x (x 8K | w 8K)

__global__ __launch_bounds__(256, 2) void qkv_hmma_kernel(
    const float* __restrict__ bq, const float* __restrict__ bk,
    const float* __restrict__ bv)
{
    extern __shared__ char smem[];
    const uint32_t sb = smem_u32(smem);
    const int tid = threadIdx.x, wid = tid >> 5, lane = tid & 31;
    const int z = blockIdx.z;
    const float* bvec = (z == 0) ? bq : (z == 1) ? bk : bv;
    __half* outp = (z == 0) ? g_q16 : (z == 1) ? g_k16 : g_v16;
    const __half* W = g_w16 + (size_t)z * DM * DM;
    const float oscale = (z == 0) ? QSCALE : 1.0f;
    const int col0 = blockIdx.x << 7;
    const int row0 = blockIdx.y << 7;

    auto issue = [&](int slab, int buf) {
        const int k0 = slab << 5;
        const uint32_t base = sb + (uint32_t)buf * 16384;
        #pragma unroll
        for (int it = 0; it < 2; it++) {
            const int idx = tid + it * 256;     // 0..511
            const int r = idx >> 2, c = idx & 3;
            uint32_t off = (uint32_t)(r * 64 + c * 16);
            off ^= (off >> 3) & 0x30;
            const size_t gx = (size_t)(row0 + r) * DM + k0 + c * 8;
            const size_t gw = (size_t)(col0 + r) * DM + k0 + c * 8;
            cp16(base + off,        g_x16 + gx);
            cp16(base + 8192 + off, W + gw);
        }
    };

    float s[16][4];
    #pragma unroll
    for (int g = 0; g < 16; g++)
        #pragma unroll
        for (int j = 0; j < 4; j++) s[g][j] = 0.0f;

    issue(0, 0);
    CP_COMMIT();

    for (int kt = 0; kt < 32; kt++) {
        if (kt) __syncthreads();
        if (kt < 31) issue(kt + 1, (kt + 1) & 1);
        CP_COMMIT();
        CP_WAIT1();
        __syncthreads();

        const uint32_t base = sb + (uint32_t)(kt & 1) * 16384;
        const int rA = (wid << 4) + (lane & 7) + ((lane >> 3) & 1) * 8;
        uint32_t ah[2][4];
        #pragma unroll
        for (int ks = 0; ks < 2; ks++) {
            const int ch = ks * 2 + (lane >> 4);
            ldsm_x4(ah[ks], swz64_addr(base, rA, ch));
        }
        #pragma unroll
        for (int nf = 0; nf < 8; nf++) {
            const int rB = nf * 16 + (lane & 7) + (lane >> 4) * 8;
            #pragma unroll
            for (int ks = 0; ks < 2; ks++) {
                const int ch = ks * 2 + ((lane >> 3) & 1);
                uint32_t w4[4];
                ldsm_x4(w4, swz64_addr(base + 8192, rB, ch));
                mma_f16(s[2*nf],   ah[ks], w4[0], w4[1]);
                mma_f16(s[2*nf+1], ah[ks], w4[2], w4[3]);
            }
        }
    }

    // epilogue: + bias (then optional q pre-scale); store fp16, head-split
    const int r1 = row0 + (wid << 4) + (lane >> 2);
    const int r2 = r1 + 8;
    const int bb1 = r1 >> 11, ss1 = r1 & (SEQ - 1);
    const int bb2 = r2 >> 11, ss2 = r2 & (SEQ - 1);
    #pragma unroll
    for (int g = 0; g < 16; g++) {
        const int c = col0 + g * 8 + (lane & 3) * 2;
        const int h = c >> 6, d = c & 63;
        float2 b2 = *(const float2*)(bvec + c);
        const size_t e1 = (((size_t)bb1 * NH + h) * SEQ + ss1) * HD + d;
        const size_t e2 = (((size_t)bb2 * NH + h) * SEQ + ss2) * HD + d;
        *(uint32_t*)&outp[e1] = h2bits(__floats2half2_rn(
            (s[g][0] + b2.x) * oscale, (s[g][1] + b2.y) * oscale));
        *(uint32_t*)&outp[e2] = h2bits(__floats2half2_rn(
            (s[g][2] + b2.x) * oscale, (s[g][3] + b2.y) * oscale));
    }
}

// ---------------------------------------------------------------------------
// Kernel 2: fp16 HMMA attention. p = ex2(s + bm), bm (fp16, premasked)
// prefetched via cp.async into smem alongside K/V (144B padded row stride:
// conflict-free quad LDS). Rowsum via ones-MMA. Unnormalized P -> fp16
// scratch; fused rescale writes fp32 attn. blockIdx.y = h*2 + b.
// ---------------------------------------------------------------------------
#define SM_Q 0
#define SM_ST 16384
#define STAGE_BYTES 34816      // K 8192 | V 8192 | BM 18432 (128 rows x 144B)
#define BM_OFF 16384
#define ATTN_SMEM_BYTES (16384 + 2*34816)

__global__ __launch_bounds__(256, 2) void attn_mma_kernel(
    float* __restrict__ outp,
    float* __restrict__ attn)
{
    extern __shared__ char smem[];
    const uint32_t sb = smem_u32(smem);

    const int tid = threadIdx.x;
    const int wid = tid >> 5, lane = tid & 31;
    const int h  = blockIdx.y >> 1;            // bias row set
    const int b  = blockIdx.y & 1;             // batch
    const int bh = b * NH + h;
    const int q0 = blockIdx.x << 7;
    const size_t bhbase = (size_t)bh * SEQ;
    const __half* bmbase = g_bmh + ((size_t)h * SEQ + q0) * SEQ;

    auto issue_kv = [&](int kt, int buf) {
        const int k0 = kt << 6;
        const uint32_t base = sb + SM_ST + (uint32_t)buf * STAGE_BYTES;
        const char* kk = (const char*)(g_k16 + (bhbase + k0) * HD);
        const char* vv = (const char*)(g_v16 + (bhbase + k0) * HD);
        #pragma unroll
        for (int it = 0; it < 2; it++) {
            const int idx = tid + it * 256;     // 0..511
            const uint32_t off = (uint32_t)(idx << 4);
            const uint32_t dst = off ^ ((off >> 3) & 0x70);
            cp16(base + dst,        kk + off);
            cp16(base + 8192 + dst, vv + off);
        }
        // bm block: 128 q-rows x 64 k (fp16), 8 chunks/row, 144B row stride
        #pragma unroll
        for (int it = 0; it < 4; it++) {
            const int idx = tid + it * 256;     // 0..1023
            const int r = idx >> 3, c = idx & 7;
            cp16(base + BM_OFF + (uint32_t)(r * 144 + c * 16),
                 bmbase + (size_t)r * SEQ + k0 + c * 8);
        }
    };

    // prologue: Q tile (128x64 fp16 = 16KB) + stage(0)
    {
        const char* qq = (const char*)(g_q16 + (bhbase + q0) * HD);
        #pragma unroll
        for (int it = 0; it < 4; it++) {
            const int idx = tid + it * 256;     // 0..1023
            const uint32_t off = (uint32_t)(idx << 4);
            const uint32_t dst = off ^ ((off >> 3) & 0x70);
            cp16(sb + SM_Q + dst, qq + off);
        }
    }
    issue_kv(0, 0);
    CP_COMMIT();

    float o[8][4];
    #pragma unroll
    for (int g = 0; g < 8; g++)
        #pragma unroll
        for (int j = 0; j < 4; j++) o[g][j] = 0.0f;
    float racc[4] = {0.0f, 0.0f, 0.0f, 0.0f};   // ones-MMA rowsum accumulator

    const int r1 = (wid << 4) + (lane >> 2);
    const int qg1 = q0 + r1, qg2 = qg1 + 8;
    __half* prow1 = g_p16 + (bhbase + qg1) * SEQ;
    __half* prow2 = g_p16 + (bhbase + qg2) * SEQ;

    const int rA = (wid << 4) + (lane & 7) + ((lane >> 3) & 1) * 8;
    const int bmo1 = r1 * 144 + (lane & 3) * 4;        // byte offsets in bm block
    const int bmo2 = (r1 + 8) * 144 + (lane & 3) * 4;

    for (int kt = 0; kt < SEQ / 64; kt++) {
        const int k0 = kt << 6;
        if (kt) __syncthreads();
        if (kt < SEQ / 64 - 1) issue_kv(kt + 1, (kt + 1) & 1);
        CP_COMMIT();
        CP_WAIT1();
        __syncthreads();

        const uint32_t base = sb + SM_ST + (uint32_t)(kt & 1) * STAGE_BYTES;
        const char* stp = smem + SM_ST + (size_t)(kt & 1) * STAGE_BYTES;

        // ---- S' = Q' K^T over 64 cols (already scaled by 0.125*log2e) ----
        float s[8][4];
        #pragma unroll
        for (int g = 0; g < 8; g++)
            #pragma unroll
            for (int j = 0; j < 4; j++) s[g][j] = 0.0f;

        #pragma unroll
        for (int ks = 0; ks < 4; ks++) {
            uint32_t qf[4];
            const int chA = ks * 2 + (lane >> 4);
            ldsm_x4(qf, swz_addr(sb + SM_Q, rA, chA));
            #pragma unroll
            for (int nf = 0; nf < 4; nf++) {
                const int rB = nf * 16 + (lane & 7) + (lane >> 4) * 8;
                const int ch = ks * 2 + ((lane >> 3) & 1);
                uint32_t k4[4];
                ldsm_x4(k4, swz_addr(base, rB, ch));
                mma_f16(s[2*nf],   qf, k4[0], k4[1]);
                mma_f16(s[2*nf+1], qf, k4[2], k4[3]);
            }
        }

        // ---- epilogue: p = ex2(s + bm[smem]); fp16 P (scratch + frags) ----
        const char* bmst = stp + BM_OFF;
        uint32_t ph[4][4];
        #pragma unroll
        for (int g = 0; g < 8; g++) {
            const int c = k0 + g * 8 + (lane & 3) * 2;
            float2 bA = __half22float2(*(const __half2*)(bmst + bmo1 + g * 16));
            float2 bB = __half22float2(*(const __half2*)(bmst + bmo2 + g * 16));
            float p0 = ex2(s[g][0] + bA.x);
            float p1 = ex2(s[g][1] + bA.y);
            float p2 = ex2(s[g][2] + bB.x);
            float p3 = ex2(s[g][3] + bB.y);
            const uint32_t h01 = h2bits(__floats2half2_rn(p0, p1));
            const uint32_t h23 = h2bits(__floats2half2_rn(p2, p3));
            *(uint32_t*)(prow1 + c) = h01;
            *(uint32_t*)(prow2 + c) = h23;
            const int ks = g >> 1, ix = (g & 1) * 2;
            ph[ks][ix + 0] = h01;
            ph[ks][ix + 1] = h23;
        }

        // ---- O += P V; rowsum += P x ones (tensor pipe) ----
        #pragma unroll
        for (int ks = 0; ks < 4; ks++) {
            mma_f16(racc, ph[ks], ONES2, ONES2);
            const int rV = ks * 16 + (lane & 7) + ((lane >> 3) & 1) * 8;
            #pragma unroll
            for (int dg = 0; dg < 4; dg++) {
                const int ch = 2 * dg + (lane >> 4);
                uint32_t v4[4];
                ldsm_x4t(v4, swz_addr(base + 8192, rV, ch));
                mma_f16(o[2*dg],   ph[ks], v4[0], v4[1]);
                mma_f16(o[2*dg+1], ph[ks], v4[2], v4[3]);
            }
        }
    }

    // ---- rowsums come straight from the ones-MMA accumulator ----
    const float inv1 = 1.0f / racc[0];
    const float inv2 = 1.0f / racc[2];

    // normalized O
    float* or1 = outp + (bhbase + qg1) * HD;
    float* or2 = outp + (bhbase + qg2) * HD;
    #pragma unroll
    for (int g = 0; g < 8; g++) {
        const int c = g * 8 + (lane & 3) * 2;
        *(float2*)(or1 + c) = make_float2(o[g][0] * inv1, o[g][1] * inv1);
        *(float2*)(or2 + c) = make_float2(o[g][2] * inv2, o[g][3] * inv2);
    }

    // ---- fused rescale: read fp16 P scratch, write fp32 normalized attn ----
    float* rs = (float*)smem;          // 128 floats; stage smem no longer needed
    __syncthreads();                   // P stores visible block-wide; smem free
    if ((lane & 3) == 0) {
        rs[r1] = inv1;
        rs[qg2 - q0] = inv2;
    }
    __syncthreads();
    #pragma unroll 1
    for (int rr = 0; rr < 16; rr++) {
        const int qr = (wid << 4) + rr;
        const float inv = rs[qr];
        const uint4* src = (const uint4*)(g_p16 + (bhbase + q0 + qr) * SEQ);
        float4* dst = (float4*)(attn + (bhbase + q0 + qr) * SEQ);
        #pragma unroll 2
        for (int c = lane; c < SEQ / 8; c += 32) {   // 8 halfs per uint4
            uint4 hv = src[c];
            const __half2* hp = (const __half2*)&hv;
            float2 f0 = __half22float2(hp[0]);
            float2 f1 = __half22float2(hp[1]);
            float2 f2 = __half22float2(hp[2]);
            float2 f3 = __half22float2(hp[3]);
            dst[c*2+0] = make_float4(f0.x*inv, f0.y*inv, f1.x*inv, f1.y*inv);
            dst[c*2+1] = make_float4(f2.x*inv, f2.y*inv, f3.x*inv, f3.y*inv);
        }
    }
}

// ---------------------------------------------------------------------------
extern "C" void kernel_launch(void* const* d_in, const int* in_sizes, int n_in,
                              void* d_out, int out_size)
{
    const float* x    = (const float*)d_in[0];
    const float* bias = (const float*)d_in[1];
    const int*   mask = (const int*)d_in[2];
    const float* wq   = (const float*)d_in[3];
    const float* bq   = (const float*)d_in[4];
    const float* wk   = (const float*)d_in[5];
    const float* bk   = (const float*)d_in[6];
    const float* wv   = (const float*)d_in[7];
    const float* bv   = (const float*)d_in[8];

    float* outp = (float*)d_out;                       // [2,16,2048,64]
    float* attn = outp + (size_t)BH * SEQ * HD;        // [2,16,2048,2048]

    cudaFuncSetAttribute(qkv_hmma_kernel,
                         cudaFuncAttributeMaxDynamicSharedMemorySize,
                         QKV_SMEM_BYTES);
    cudaFuncSetAttribute(attn_mma_kernel,
                         cudaFuncAttributeMaxDynamicSharedMemorySize,
                         ATTN_SMEM_BYTES);

    // 0a) round x / W to fp16
    split_src_kernel<<<dim3(2048, 4), 256>>>(x, wq, wk, wv);

    // 0b) premask + prescale bias (fp16)
    prep_bias_kernel<<<dim3(SEQ * SEQ / 2 / 256), 256>>>(bias, mask);

    // 1) QKV projections (single-term fp16 HMMA); q pre-scaled
    qkv_hmma_kernel<<<dim3(DM / 128, (BSZ * SEQ) / 128, 3), 256,
                      QKV_SMEM_BYTES>>>(bq, bk, bv);

    // 2) fp16 HMMA fused attention + fused rescale
    attn_mma_kernel<<<dim3(SEQ / 128, BH), 256, ATTN_SMEM_BYTES>>>(
        outp, attn);
}

// round 15
// speedup vs baseline: 1.8594x; 1.0545x over previous
#include <cuda_runtime.h>
#include <cuda_fp16.h>
#include <cstdint>

#define BSZ 2
#define NH 16
#define SEQ 2048
#define DM 1024
#define HD 64
#define BH (BSZ*NH)

// Scratch (device globals — no allocations allowed)
__device__ __half g_x16[BSZ*SEQ*DM];    // x (fp16)
__device__ __half g_w16[3*DM*DM];       // W (fp16)
__device__ __half g_q16[BH * SEQ * HD]; // q pre-scaled by 0.125*log2(e)
__device__ __half g_k16[BH * SEQ * HD];
__device__ __half g_v16[BH * SEQ * HD];
__device__ __half g_p16[(size_t)BH * SEQ * SEQ];   // unnormalized P scratch (fp16)
__device__ __half g_bmh[(size_t)NH * SEQ * SEQ];   // premasked bias*log2e (fp16)

#define LOG2E 1.44269504f
#define QSCALE (0.125f * LOG2E)
#define ONES2  0x3C003C00u      // half2(1.0, 1.0)
#define MASKV  (-60000.0f)      // fp16-safe "minus infinity" (ex2 -> 0)

// ---- helpers -----------------------------------------------------------------
__device__ __forceinline__ uint32_t h2bits(__half2 v) {
    return *reinterpret_cast<uint32_t*>(&v);
}
__device__ __forceinline__ float ex2(float x) {
    float y; asm("ex2.approx.ftz.f32 %0, %1;" : "=f"(y) : "f"(x)); return y;
}
__device__ __forceinline__ uint32_t smem_u32(const void* p) {
    uint32_t a;
    asm("{ .reg .u64 t; cvta.to.shared.u64 t, %1; cvt.u32.u64 %0, t; }"
        : "=r"(a) : "l"(p));
    return a;
}
// 128B-row tiles: XOR 16B-chunk by (row&7)
__device__ __forceinline__ uint32_t swz_addr(uint32_t base, int row, int chunk) {
    uint32_t off = (uint32_t)(row * 128 + chunk * 16);
    return base + (off ^ ((off >> 3) & 0x70));
}
// 64B-row tiles: SW64 swizzle
__device__ __forceinline__ uint32_t swz64_addr(uint32_t base, int row, int chunk) {
    uint32_t off = (uint32_t)(row * 64 + chunk * 16);
    return base + (off ^ ((off >> 3) & 0x30));
}
__device__ __forceinline__ void ldsm_x4(uint32_t* r, uint32_t a) {
    asm volatile("ldmatrix.sync.aligned.m8n8.x4.shared.b16 {%0,%1,%2,%3}, [%4];"
        : "=r"(r[0]), "=r"(r[1]), "=r"(r[2]), "=r"(r[3]) : "r"(a));
}
__device__ __forceinline__ void ldsm_x4t(uint32_t* r, uint32_t a) {
    asm volatile("ldmatrix.sync.aligned.m8n8.x4.trans.shared.b16 {%0,%1,%2,%3}, [%4];"
        : "=r"(r[0]), "=r"(r[1]), "=r"(r[2]), "=r"(r[3]) : "r"(a));
}
__device__ __forceinline__ void mma_f16(float* d, const uint32_t* a,
                                        uint32_t b0, uint32_t b1) {
    asm volatile("mma.sync.aligned.m16n8k16.row.col.f32.f16.f16.f32 "
        "{%0,%1,%2,%3}, {%4,%5,%6,%7}, {%8,%9}, {%0,%1,%2,%3};"
        : "+f"(d[0]), "+f"(d[1]), "+f"(d[2]), "+f"(d[3])
        : "r"(a[0]), "r"(a[1]), "r"(a[2]), "r"(a[3]), "r"(b0), "r"(b1));
}
__device__ __forceinline__ void cp16(uint32_t dst, const void* src) {
    asm volatile("cp.async.cg.shared.global [%0], [%1], 16;"
                 :: "r"(dst), "l"(src) : "memory");
}
#define CP_COMMIT() asm volatile("cp.async.commit_group;" ::: "memory")
#define CP_WAIT1()  asm volatile("cp.async.wait_group 1;" ::: "memory")

// ---------------------------------------------------------------------------
// Kernel 0a: round x and W to fp16.
// ---------------------------------------------------------------------------
__global__ __launch_bounds__(256) void split_src_kernel(
    const float* __restrict__ x,
    const float* __restrict__ wq, const float* __restrict__ wk,
    const float* __restrict__ wv)
{
    const int z = blockIdx.y;
    const float* src = (z == 0) ? x : (z == 1) ? wq : (z == 2) ? wk : wv;
    uint32_t* dst = (z == 0) ? (uint32_t*)g_x16
                             : (uint32_t*)(g_w16 + (size_t)(z - 1) * DM * DM);
    const size_t n2 = (z == 0) ? (size_t)BSZ * SEQ * DM / 2
                               : (size_t)DM * DM / 2;
    for (size_t i = (size_t)blockIdx.x * 256 + threadIdx.x; i < n2;
         i += (size_t)gridDim.x * 256) {
        float2 v = ((const float2*)src)[i];
        dst[i] = h2bits(__floats2half2_rn(v.x, v.y));
    }
}

// ---------------------------------------------------------------------------
// Kernel 0b: premask + prescale bias to fp16: bm = mask ? bias*log2e : -60000.
// ---------------------------------------------------------------------------
__global__ __launch_bounds__(256) void prep_bias_kernel(
    const float* __restrict__ bias, const int* __restrict__ mask)
{
    const size_t i = (size_t)blockIdx.x * 256 + threadIdx.x;  // over SEQ*SEQ/2
    int2 m = ((const int2*)mask)[i];
    #pragma unroll 4
    for (int h = 0; h < NH; h++) {
        float2 bv = ((const float2*)(bias + (size_t)h * SEQ * SEQ))[i];
        float ox = m.x ? bv.x * LOG2E : MASKV;
        float oy = m.y ? bv.y * LOG2E : MASKV;
        ((uint32_t*)(g_bmh + (size_t)h * SEQ * SEQ))[i] =
            h2bits(__floats2half2_rn(ox, oy));
    }
}

// ---------------------------------------------------------------------------
// Kernel 1: QKV projection via single-term fp16 HMMA.
// 128x128 tile, K-slab 32, 64B-row smem (SW64), double-buffered, 2 CTAs/SM.
// Q output pre-scaled by 0.125*log2e.
// ---------------------------------------------------------------------------
#define QKV_SMEM_BYTES 32768     // 2 stages x (x 8K | w 8K)

__global__ __launch_bounds__(256, 2) void qkv_hmma_kernel(
    const float* __restrict__ bq, const float* __restrict__ bk,
    const float* __restrict__ bv)
{
    extern __shared__ char smem[];
    const uint32_t sb = smem_u32(smem);
    const int tid = threadIdx.x, wid = tid >> 5, lane = tid & 31;
    const int z = blockIdx.z;
    const float* bvec = (z == 0) ? bq : (z == 1) ? bk : bv;
    __half* outp = (z == 0) ? g_q16 : (z == 1) ? g_k16 : g_v16;
    const __half* W = g_w16 + (size_t)z * DM * DM;
    const float oscale = (z == 0) ? QSCALE : 1.0f;
    const int col0 = blockIdx.x << 7;
    const int row0 = blockIdx.y << 7;

    auto issue = [&](int slab, int buf) {
        const int k0 = slab << 5;
        const uint32_t base = sb + (uint32_t)buf * 16384;
        #pragma unroll
        for (int it = 0; it < 2; it++) {
            const int idx = tid + it * 256;     // 0..511
            const int r = idx >> 2, c = idx & 3;
            uint32_t off = (uint32_t)(r * 64 + c * 16);
            off ^= (off >> 3) & 0x30;
            const size_t gx = (size_t)(row0 + r) * DM + k0 + c * 8;
            const size_t gw = (size_t)(col0 + r) * DM + k0 + c * 8;
            cp16(base + off,        g_x16 + gx);
            cp16(base + 8192 + off, W + gw);
        }
    };

    float s[16][4];
    #pragma unroll
    for (int g = 0; g < 16; g++)
        #pragma unroll
        for (int j = 0; j < 4; j++) s[g][j] = 0.0f;

    issue(0, 0);
    CP_COMMIT();

    for (int kt = 0; kt < 32; kt++) {
        if (kt) __syncthreads();
        if (kt < 31) issue(kt + 1, (kt + 1) & 1);
        CP_COMMIT();
        CP_WAIT1();
        __syncthreads();

        const uint32_t base = sb + (uint32_t)(kt & 1) * 16384;
        const int rA = (wid << 4) + (lane & 7) + ((lane >> 3) & 1) * 8;
        uint32_t ah[2][4];
        #pragma unroll
        for (int ks = 0; ks < 2; ks++) {
            const int ch = ks * 2 + (lane >> 4);
            ldsm_x4(ah[ks], swz64_addr(base, rA, ch));
        }
        #pragma unroll
        for (int nf = 0; nf < 8; nf++) {
            const int rB = nf * 16 + (lane & 7) + (lane >> 4) * 8;
            #pragma unroll
            for (int ks = 0; ks < 2; ks++) {
                const int ch = ks * 2 + ((lane >> 3) & 1);
                uint32_t w4[4];
                ldsm_x4(w4, swz64_addr(base + 8192, rB, ch));
                mma_f16(s[2*nf],   ah[ks], w4[0], w4[1]);
                mma_f16(s[2*nf+1], ah[ks], w4[2], w4[3]);
            }
        }
    }

    // epilogue: + bias (then optional q pre-scale); store fp16, head-split
    const int r1 = row0 + (wid << 4) + (lane >> 2);
    const int r2 = r1 + 8;
    const int bb1 = r1 >> 11, ss1 = r1 & (SEQ - 1);
    const int bb2 = r2 >> 11, ss2 = r2 & (SEQ - 1);
    #pragma unroll
    for (int g = 0; g < 16; g++) {
        const int c = col0 + g * 8 + (lane & 3) * 2;
        const int h = c >> 6, d = c & 63;
        float2 b2 = *(const float2*)(bvec + c);
        const size_t e1 = (((size_t)bb1 * NH + h) * SEQ + ss1) * HD + d;
        const size_t e2 = (((size_t)bb2 * NH + h) * SEQ + ss2) * HD + d;
        *(uint32_t*)&outp[e1] = h2bits(__floats2half2_rn(
            (s[g][0] + b2.x) * oscale, (s[g][1] + b2.y) * oscale));
        *(uint32_t*)&outp[e2] = h2bits(__floats2half2_rn(
            (s[g][2] + b2.x) * oscale, (s[g][3] + b2.y) * oscale));
    }
}

// ---------------------------------------------------------------------------
// Kernel 2: fp16 HMMA attention. p = ex2(s + bm) with bm pipelined in smem.
// P tile staged in XOR-swizzled smem, written to scratch with coalesced
// STG.128 (was 16 scattered STG.32/thread). Rowsum via ones-MMA.
// Fused rescale reads fp16 scratch, writes fp32 attn. blockIdx.y = h*2 + b.
// ---------------------------------------------------------------------------
#define SM_Q  0
#define SM_P  16384
#define SM_ST 32768
#define STAGE_BYTES 34816      // K 8192 | V 8192 | BM 18432 (128 rows x 144B)
#define BM_OFF 16384
#define ATTN_SMEM_BYTES (32768 + 2*34816)

__global__ __launch_bounds__(256, 2) void attn_mma_kernel(
    float* __restrict__ outp,
    float* __restrict__ attn)
{
    extern __shared__ char smem[];
    const uint32_t sb = smem_u32(smem);

    const int tid = threadIdx.x;
    const int wid = tid >> 5, lane = tid & 31;
    const int h  = blockIdx.y >> 1;            // bias row set
    const int b  = blockIdx.y & 1;             // batch
    const int bh = b * NH + h;
    const int q0 = blockIdx.x << 7;
    const size_t bhbase = (size_t)bh * SEQ;
    const __half* bmbase = g_bmh + ((size_t)h * SEQ + q0) * SEQ;

    auto issue_kv = [&](int kt, int buf) {
        const int k0 = kt << 6;
        const uint32_t base = sb + SM_ST + (uint32_t)buf * STAGE_BYTES;
        const char* kk = (const char*)(g_k16 + (bhbase + k0) * HD);
        const char* vv = (const char*)(g_v16 + (bhbase + k0) * HD);
        #pragma unroll
        for (int it = 0; it < 2; it++) {
            const int idx = tid + it * 256;     // 0..511
            const uint32_t off = (uint32_t)(idx << 4);
            const uint32_t dst = off ^ ((off >> 3) & 0x70);
            cp16(base + dst,        kk + off);
            cp16(base + 8192 + dst, vv + off);
        }
        // bm block: 128 q-rows x 64 k (fp16), 8 chunks/row, 144B row stride
        #pragma unroll
        for (int it = 0; it < 4; it++) {
            const int idx = tid + it * 256;     // 0..1023
            const int r = idx >> 3, c = idx & 7;
            cp16(base + BM_OFF + (uint32_t)(r * 144 + c * 16),
                 bmbase + (size_t)r * SEQ + k0 + c * 8);
        }
    };

    // prologue: Q tile (128x64 fp16 = 16KB) + stage(0)
    {
        const char* qq = (const char*)(g_q16 + (bhbase + q0) * HD);
        #pragma unroll
        for (int it = 0; it < 4; it++) {
            const int idx = tid + it * 256;     // 0..1023
            const uint32_t off = (uint32_t)(idx << 4);
            const uint32_t dst = off ^ ((off >> 3) & 0x70);
            cp16(sb + SM_Q + dst, qq + off);
        }
    }
    issue_kv(0, 0);
    CP_COMMIT();

    float o[8][4];
    #pragma unroll
    for (int g = 0; g < 8; g++)
        #pragma unroll
        for (int j = 0; j < 4; j++) o[g][j] = 0.0f;
    float racc[4] = {0.0f, 0.0f, 0.0f, 0.0f};   // ones-MMA rowsum accumulator

    const int r1 = (wid << 4) + (lane >> 2);
    const int qg1 = q0 + r1, qg2 = qg1 + 8;

    const int rA = (wid << 4) + (lane & 7) + ((lane >> 3) & 1) * 8;
    const int bmo1 = r1 * 144 + (lane & 3) * 4;        // byte offsets in bm block
    const int bmo2 = (r1 + 8) * 144 + (lane & 3) * 4;
    // P staging: XOR-swizzled 128B rows; same swizzle sel for r1 and r1+8
    const int psw = (lane >> 2) & 7;
    const uint32_t pb1 = sb + SM_P + (uint32_t)(r1 * 128 + (lane & 3) * 4);
    const uint32_t pb2 = pb1 + 8 * 128;

    for (int kt = 0; kt < SEQ / 64; kt++) {
        const int k0 = kt << 6;
        if (kt) __syncthreads();               // stage + P-smem free
        if (kt < SEQ / 64 - 1) issue_kv(kt + 1, (kt + 1) & 1);
        CP_COMMIT();
        CP_WAIT1();
        __syncthreads();

        const uint32_t base = sb + SM_ST + (uint32_t)(kt & 1) * STAGE_BYTES;
        const char* stp = smem + SM_ST + (size_t)(kt & 1) * STAGE_BYTES;

        // ---- S' = Q' K^T over 64 cols (already scaled by 0.125*log2e) ----
        float s[8][4];
        #pragma unroll
        for (int g = 0; g < 8; g++)
            #pragma unroll
            for (int j = 0; j < 4; j++) s[g][j] = 0.0f;

        #pragma unroll
        for (int ks = 0; ks < 4; ks++) {
            uint32_t qf[4];
            const int chA = ks * 2 + (lane >> 4);
            ldsm_x4(qf, swz_addr(sb + SM_Q, rA, chA));
            #pragma unroll
            for (int nf = 0; nf < 4; nf++) {
                const int rB = nf * 16 + (lane & 7) + (lane >> 4) * 8;
                const int ch = ks * 2 + ((lane >> 3) & 1);
                uint32_t k4[4];
                ldsm_x4(k4, swz_addr(base, rB, ch));
                mma_f16(s[2*nf],   qf, k4[0], k4[1]);
                mma_f16(s[2*nf+1], qf, k4[2], k4[3]);
            }
        }

        // ---- epilogue: p = ex2(s + bm[smem]); P -> swizzled smem + frags ----
        const char* bmst = stp + BM_OFF;
        uint32_t ph[4][4];
        #pragma unroll
        for (int g = 0; g < 8; g++) {
            float2 bA = __half22float2(*(const __half2*)(bmst + bmo1 + g * 16));
            float2 bB = __half22float2(*(const __half2*)(bmst + bmo2 + g * 16));
            float p0 = ex2(s[g][0] + bA.x);
            float p1 = ex2(s[g][1] + bA.y);
            float p2 = ex2(s[g][2] + bB.x);
            float p3 = ex2(s[g][3] + bB.y);
            const uint32_t h01 = h2bits(__floats2half2_rn(p0, p1));
            const uint32_t h23 = h2bits(__floats2half2_rn(p2, p3));
            const uint32_t go = (uint32_t)((g ^ psw) << 4);
            *(uint32_t*)(smem + (pb1 - sb) + go) = h01;
            *(uint32_t*)(smem + (pb2 - sb) + go) = h23;
            const int ks = g >> 1, ix = (g & 1) * 2;
            ph[ks][ix + 0] = h01;
            ph[ks][ix + 1] = h23;
        }

        // ---- O += P V; rowsum += P x ones (tensor pipe) ----
        #pragma unroll
        for (int ks = 0; ks < 4; ks++) {
            mma_f16(racc, ph[ks], ONES2, ONES2);
            const int rV = ks * 16 + (lane & 7) + ((lane >> 3) & 1) * 8;
            #pragma unroll
            for (int dg = 0; dg < 4; dg++) {
                const int ch = 2 * dg + (lane >> 4);
                uint32_t v4[4];
                ldsm_x4t(v4, swz_addr(base + 8192, rV, ch));
                mma_f16(o[2*dg],   ph[ks], v4[0], v4[1]);
                mma_f16(o[2*dg+1], ph[ks], v4[2], v4[3]);
            }
        }

        // ---- coalesced P tile store: smem -> g_p16 (STG.128) ----
        __syncthreads();
        #pragma unroll
        for (int it = 0; it < 4; it++) {
            const int idx = tid + it * 256;    // 0..1023 chunks of 16B
            const int r = idx >> 3, c = idx & 7;
            uint4 v = *(const uint4*)(smem + SM_P + r * 128 + ((c ^ (r & 7)) << 4));
            *(uint4*)(g_p16 + (bhbase + q0 + r) * SEQ + k0 + c * 8) = v;
        }
    }

    // ---- rowsums come straight from the ones-MMA accumulator ----
    const float inv1 = 1.0f / racc[0];
    const float inv2 = 1.0f / racc[2];

    // normalized O
    float* or1 = outp + (bhbase + qg1) * HD;
    float* or2 = outp + (bhbase + qg2) * HD;
    #pragma unroll
    for (int g = 0; g < 8; g++) {
        const int c = g * 8 + (lane & 3) * 2;
        *(float2*)(or1 + c) = make_float2(o[g][0] * inv1, o[g][1] * inv1);
        *(float2*)(or2 + c) = make_float2(o[g][2] * inv2, o[g][3] * inv2);
    }

    // ---- fused rescale: read fp16 P scratch, write fp32 normalized attn ----
    float* rs = (float*)smem;          // 128 floats; stage smem no longer needed
    __syncthreads();                   // P stores done; smem free
    if ((lane & 3) == 0) {
        rs[r1] = inv1;
        rs[qg2 - q0] = inv2;
    }
    __syncthreads();
    #pragma unroll 1
    for (int rr = 0; rr < 16; rr++) {
        const int qr = (wid << 4) + rr;
        const float inv = rs[qr];
        const uint4* src = (const uint4*)(g_p16 + (bhbase + q0 + qr) * SEQ);
        float4* dst = (float4*)(attn + (bhbase + q0 + qr) * SEQ);
        #pragma unroll 2
        for (int c = lane; c < SEQ / 8; c += 32) {   // 8 halfs per uint4
            uint4 hv = src[c];
            const __half2* hp = (const __half2*)&hv;
            float2 f0 = __half22float2(hp[0]);
            float2 f1 = __half22float2(hp[1]);
            float2 f2 = __half22float2(hp[2]);
            float2 f3 = __half22float2(hp[3]);
            dst[c*2+0] = make_float4(f0.x*inv, f0.y*inv, f1.x*inv, f1.y*inv);
            dst[c*2+1] = make_float4(f2.x*inv, f2.y*inv, f3.x*inv, f3.y*inv);
        }
    }
}

// ---------------------------------------------------------------------------
extern "C" void kernel_launch(void* const* d_in, const int* in_sizes, int n_in,
                              void* d_out, int out_size)
{
    const float* x    = (const float*)d_in[0];
    const float* bias = (const float*)d_in[1];
    const int*   mask = (const int*)d_in[2];
    const float* wq   = (const float*)d_in[3];
    const float* bq   = (const float*)d_in[4];
    const float* wk   = (const float*)d_in[5];
    const float* bk   = (const float*)d_in[6];
    const float* wv   = (const float*)d_in[7];
    const float* bv   = (const float*)d_in[8];

    float* outp = (float*)d_out;                       // [2,16,2048,64]
    float* attn = outp + (size_t)BH * SEQ * HD;        // [2,16,2048,2048]

    cudaFuncSetAttribute(qkv_hmma_kernel,
                         cudaFuncAttributeMaxDynamicSharedMemorySize,
                         QKV_SMEM_BYTES);
    cudaFuncSetAttribute(attn_mma_kernel,
                         cudaFuncAttributeMaxDynamicSharedMemorySize,
                         ATTN_SMEM_BYTES);

    // 0a) round x / W to fp16
    split_src_kernel<<<dim3(2048, 4), 256>>>(x, wq, wk, wv);

    // 0b) premask + prescale bias (fp16)
    prep_bias_kernel<<<dim3(SEQ * SEQ / 2 / 256), 256>>>(bias, mask);

    // 1) QKV projections (single-term fp16 HMMA); q pre-scaled
    qkv_hmma_kernel<<<dim3(DM / 128, (BSZ * SEQ) / 128, 3), 256,
                      QKV_SMEM_BYTES>>>(bq, bk, bv);

    // 2) fp16 HMMA fused attention + fused rescale
    attn_mma_kernel<<<dim3(SEQ / 128, BH), 256, ATTN_SMEM_BYTES>>>(
        outp, attn);
}